// round 1
// baseline (speedup 1.0000x reference)
#include <cuda_runtime.h>
#include <math.h>

#define NN 50000
#define EE 200000

// ---------------- scratch (static device globals; allocation-free) ----------------
__device__ float g_bufA[(size_t)NN * 1024];
__device__ float g_bufB[(size_t)NN * 1024];
__device__ float g_deg[NN];
__device__ float g_dis[NN];
__device__ float g_norm[EE];

// ---------------- prep kernels ----------------
__global__ void k_deg_init(float* __restrict__ deg) {
    int i = blockIdx.x * blockDim.x + threadIdx.x;
    if (i < NN) deg[i] = 1.0f;   // self-loop contributes 1 to every node
}

__global__ void k_deg_edges(const int* __restrict__ col, float* __restrict__ deg) {
    int e = blockIdx.x * blockDim.x + threadIdx.x;
    if (e < EE) atomicAdd(&deg[col[e]], 1.0f);
}

__global__ void k_dis(const float* __restrict__ deg, float* __restrict__ dis) {
    int i = blockIdx.x * blockDim.x + threadIdx.x;
    if (i < NN) dis[i] = rsqrtf(deg[i]);   // deg >= 1 always
}

__global__ void k_norm(const int* __restrict__ row, const int* __restrict__ col,
                       const float* __restrict__ dis, float* __restrict__ nrm) {
    int e = blockIdx.x * blockDim.x + threadIdx.x;
    if (e < EE) nrm[e] = dis[row[e]] * dis[col[e]];
}

// ---------------- aggregation ----------------
// Pass 1: t[i,f] = (bias[f] +) dis[i]^2 * h[i,f]   (full overwrite; self-loop term)
template <bool BIAS>
__global__ void k_selfloop(const float* __restrict__ h, float* __restrict__ t,
                           const float* __restrict__ dis, const float* __restrict__ bias,
                           int F) {
    int idx = blockIdx.x * blockDim.x + threadIdx.x;
    int total = NN * F;
    if (idx >= total) return;
    int i = idx / F;
    int f = idx - i * F;
    float d = dis[i];
    float v = d * d * h[idx];
    if (BIAS) v += bias[f];
    t[idx] = v;
}

// Pass 2: t[col[e],f] += norm[e] * h[row[e],f]  for all edges
template <int F>
__global__ void k_edge_agg(const float* __restrict__ h, float* __restrict__ t,
                           const int* __restrict__ row, const int* __restrict__ col,
                           const float* __restrict__ nrm) {
    int idx = blockIdx.x * blockDim.x + threadIdx.x;
    if (idx >= EE * F) return;
    int e = idx / F;           // compile-time F -> cheap division
    int f = idx - e * F;
    atomicAdd(&t[col[e] * F + f], nrm[e] * h[row[e] * F + f]);
}

__global__ void k_relu(float* __restrict__ t, int n) {
    int i = blockIdx.x * blockDim.x + threadIdx.x;
    if (i < n) t[i] = fmaxf(t[i], 0.0f);
}

// ---------------- GEMM: C[MxN] = A[MxK] @ B[KxN] (+bias)(+relu) ----------------
// BM=128, BN=64, BK=16, 256 threads, 8x4 per thread. Requires K%16==0, N%64==0.
template <bool RELU, bool BIAS>
__global__ void __launch_bounds__(256) k_gemm(
    const float* __restrict__ A, const float* __restrict__ B,
    const float* __restrict__ bias, float* __restrict__ C,
    int M, int N, int K)
{
    constexpr int BM = 128, BN = 64, BK = 16, TM = 8, TN = 4;
    constexpr int AST = BM + 4;          // pad to soften transposed-store conflicts
    __shared__ float As[BK * AST];
    __shared__ float Bs[BK * BN];

    const int tid = threadIdx.x;
    const int bm = blockIdx.y * BM;
    const int bn = blockIdx.x * BN;
    const int tx = tid & 15;             // n-tile index (0..15)
    const int ty = tid >> 4;             // m-tile index (0..15)

    const int ar = tid >> 2;             // A-load row within tile (0..63), +64 second half
    const int ac = (tid & 3) * 4;        // A-load k offset (float4)
    const int br = tid >> 4;             // B-load k row (0..15)
    const int bc = (tid & 15) * 4;       // B-load n offset (float4)

    float acc[TM][TN] = {};

    for (int kt = 0; kt < K; kt += BK) {
        // A tile (transposed store As[k][m])
        #pragma unroll
        for (int i = 0; i < 2; i++) {
            int r = ar + i * 64;
            int gr = bm + r;
            float4 v = make_float4(0.f, 0.f, 0.f, 0.f);
            if (gr < M) v = *(const float4*)(A + (size_t)gr * K + kt + ac);
            As[(ac + 0) * AST + r] = v.x;
            As[(ac + 1) * AST + r] = v.y;
            As[(ac + 2) * AST + r] = v.z;
            As[(ac + 3) * AST + r] = v.w;
        }
        // B tile
        {
            float4 v = *(const float4*)(B + (size_t)(kt + br) * N + bn + bc);
            *(float4*)(Bs + br * BN + bc) = v;
        }
        __syncthreads();

        #pragma unroll
        for (int k = 0; k < BK; k++) {
            float ra[TM], rb[TN];
            float4 a0 = *(const float4*)(As + k * AST + ty * TM);
            float4 a1 = *(const float4*)(As + k * AST + ty * TM + 4);
            ra[0] = a0.x; ra[1] = a0.y; ra[2] = a0.z; ra[3] = a0.w;
            ra[4] = a1.x; ra[5] = a1.y; ra[6] = a1.z; ra[7] = a1.w;
            float4 b0 = *(const float4*)(Bs + k * BN + tx * TN);
            rb[0] = b0.x; rb[1] = b0.y; rb[2] = b0.z; rb[3] = b0.w;
            #pragma unroll
            for (int m = 0; m < TM; m++)
                #pragma unroll
                for (int n = 0; n < TN; n++)
                    acc[m][n] += ra[m] * rb[n];
        }
        __syncthreads();
    }

    float bv[TN] = {0.f, 0.f, 0.f, 0.f};
    if (BIAS) {
        float4 t = *(const float4*)(bias + bn + tx * TN);
        bv[0] = t.x; bv[1] = t.y; bv[2] = t.z; bv[3] = t.w;
    }
    #pragma unroll
    for (int m = 0; m < TM; m++) {
        int gr = bm + ty * TM + m;
        if (gr < M) {
            float4 o;
            o.x = acc[m][0] + bv[0];
            o.y = acc[m][1] + bv[1];
            o.z = acc[m][2] + bv[2];
            o.w = acc[m][3] + bv[3];
            if (RELU) {
                o.x = fmaxf(o.x, 0.f); o.y = fmaxf(o.y, 0.f);
                o.z = fmaxf(o.z, 0.f); o.w = fmaxf(o.w, 0.f);
            }
            *(float4*)(C + (size_t)gr * N + bn + tx * TN) = o;
        }
    }
}

// ---------------- layer-0 GEMM (K=3, Fout=64, bias+relu) ----------------
__global__ void k_l0_gemm(const float* __restrict__ t, const float* __restrict__ W,
                          const float* __restrict__ b, float* __restrict__ y) {
    int idx = blockIdx.x * blockDim.x + threadIdx.x;
    if (idx >= NN * 64) return;
    int i = idx >> 6;
    int j = idx & 63;
    float acc = b[j];
    acc += t[i * 3 + 0] * W[0 * 64 + j];
    acc += t[i * 3 + 1] * W[1 * 64 + j];
    acc += t[i * 3 + 2] * W[2 * 64 + j];
    y[idx] = fmaxf(acc, 0.f);
}

// ---------------- layer-7 GEMM (K=256, Fout=2, no bias here) --------------
// warp per row: lane l handles k = l*4 and (l+32)*4 float4 chunks
__global__ void k_l7_gemm(const float* __restrict__ x, const float* __restrict__ W,
                          float* __restrict__ h) {
    int gwarp = (blockIdx.x * blockDim.x + threadIdx.x) >> 5;
    int lane = threadIdx.x & 31;
    if (gwarp >= NN) return;
    const float4* xr = (const float4*)(x + (size_t)gwarp * 256);
    float a0 = 0.f, a1 = 0.f;
    #pragma unroll
    for (int it = 0; it < 2; it++) {
        int c4 = lane + it * 32;       // 0..63
        float4 v = xr[c4];
        int k = c4 * 4;
        a0 += v.x * W[(k + 0) * 2 + 0] + v.y * W[(k + 1) * 2 + 0]
            + v.z * W[(k + 2) * 2 + 0] + v.w * W[(k + 3) * 2 + 0];
        a1 += v.x * W[(k + 0) * 2 + 1] + v.y * W[(k + 1) * 2 + 1]
            + v.z * W[(k + 2) * 2 + 1] + v.w * W[(k + 3) * 2 + 1];
    }
    #pragma unroll
    for (int off = 16; off > 0; off >>= 1) {
        a0 += __shfl_down_sync(0xFFFFFFFFu, a0, off);
        a1 += __shfl_down_sync(0xFFFFFFFFu, a1, off);
    }
    if (lane == 0) {
        h[gwarp * 2 + 0] = a0;
        h[gwarp * 2 + 1] = a1;
    }
}

// ---------------- host orchestration ----------------
static inline void launch_gemm(const float* A, const float* B, const float* bias,
                               float* C, int M, int Nc, int K, bool relu_bias) {
    dim3 grid(Nc / 64, (M + 127) / 128);
    if (relu_bias) k_gemm<true, true><<<grid, 256>>>(A, B, bias, C, M, Nc, K);
    else           k_gemm<false, false><<<grid, 256>>>(A, B, nullptr, C, M, Nc, K);
}

extern "C" void kernel_launch(void* const* d_in, const int* in_sizes, int n_in,
                              void* d_out, int out_size) {
    const float* x = (const float*)d_in[0];
    const int* ei  = (const int*)d_in[1];
    const int* row = ei;           // edge_index[0] = source
    const int* col = ei + EE;      // edge_index[1] = target
    const float* W[8];
    const float* b[8];
    for (int i = 0; i < 8; i++) {
        W[i] = (const float*)d_in[2 + 2 * i];
        b[i] = (const float*)d_in[3 + 2 * i];
    }
    float *bufA, *bufB, *deg, *dis, *nrm;
    cudaGetSymbolAddress((void**)&bufA, g_bufA);
    cudaGetSymbolAddress((void**)&bufB, g_bufB);
    cudaGetSymbolAddress((void**)&deg,  g_deg);
    cudaGetSymbolAddress((void**)&dis,  g_dis);
    cudaGetSymbolAddress((void**)&nrm,  g_norm);
    float* out = (float*)d_out;

    // ---- normalization prep (shared by all layers) ----
    k_deg_init<<<(NN + 255) / 256, 256>>>(deg);
    k_deg_edges<<<(EE + 255) / 256, 256>>>(col, deg);
    k_dis<<<(NN + 255) / 256, 256>>>(deg, dis);
    k_norm<<<(EE + 255) / 256, 256>>>(row, col, dis, nrm);

    // ---- L0: 3 -> 64  (aggregate@3, then GEMM+bias+relu) ----
    k_selfloop<false><<<(NN * 3 + 255) / 256, 256>>>(x, bufA, dis, nullptr, 3);
    k_edge_agg<3><<<(EE * 3 + 255) / 256, 256>>>(x, bufA, row, col, nrm);
    k_l0_gemm<<<(NN * 64 + 255) / 256, 256>>>(bufA, W[0], b[0], bufB);

    // ---- L1: 64 -> 64 ----
    k_selfloop<false><<<(NN * 64 + 255) / 256, 256>>>(bufB, bufA, dis, nullptr, 64);
    k_edge_agg<64><<<(EE * 64 + 255) / 256, 256>>>(bufB, bufA, row, col, nrm);
    launch_gemm(bufA, W[1], b[1], bufB, NN, 64, 64, true);

    // ---- L2: 64 -> 64 ----
    k_selfloop<false><<<(NN * 64 + 255) / 256, 256>>>(bufB, bufA, dis, nullptr, 64);
    k_edge_agg<64><<<(EE * 64 + 255) / 256, 256>>>(bufB, bufA, row, col, nrm);
    launch_gemm(bufA, W[2], b[2], bufB, NN, 64, 64, true);

    // ---- L3: 64 -> 128 ----
    k_selfloop<false><<<(NN * 64 + 255) / 256, 256>>>(bufB, bufA, dis, nullptr, 64);
    k_edge_agg<64><<<(EE * 64 + 255) / 256, 256>>>(bufB, bufA, row, col, nrm);
    launch_gemm(bufA, W[3], b[3], bufB, NN, 128, 64, true);

    // ---- L4: 128 -> 1024  (aggregate@128, then GEMM) ----
    k_selfloop<false><<<(NN * 128 + 255) / 256, 256>>>(bufB, bufA, dis, nullptr, 128);
    k_edge_agg<128><<<(EE * 128 + 255) / 256, 256>>>(bufB, bufA, row, col, nrm);
    launch_gemm(bufA, W[4], b[4], bufB, NN, 1024, 128, true);

    // ---- L5: 1024 -> 512  (GEMM, then aggregate@512 with fused bias, relu) ----
    launch_gemm(bufB, W[5], nullptr, bufA, NN, 512, 1024, false);
    k_selfloop<true><<<(NN * 512 + 255) / 256, 256>>>(bufA, bufB, dis, b[5], 512);
    k_edge_agg<512><<<(EE * 512 + 255) / 256, 256>>>(bufA, bufB, row, col, nrm);
    k_relu<<<(NN * 512 + 255) / 256, 256>>>(bufB, NN * 512);

    // ---- L6: 512 -> 256 ----
    launch_gemm(bufB, W[6], nullptr, bufA, NN, 256, 512, false);
    k_selfloop<true><<<(NN * 256 + 255) / 256, 256>>>(bufA, bufB, dis, b[6], 256);
    k_edge_agg<256><<<(EE * 256 + 255) / 256, 256>>>(bufA, bufB, row, col, nrm);
    k_relu<<<(NN * 256 + 255) / 256, 256>>>(bufB, NN * 256);

    // ---- L7: 256 -> 2 (GEMM, then aggregate@2 with fused bias; no relu) ----
    k_l7_gemm<<<(NN * 32 + 255) / 256, 256>>>(bufB, W[7], bufA);
    k_selfloop<true><<<(NN * 2 + 255) / 256, 256>>>(bufA, out, dis, b[7], 2);
    k_edge_agg<2><<<(EE * 2 + 255) / 256, 256>>>(bufA, out, row, col, nrm);
}

// round 6
// speedup vs baseline: 1.4015x; 1.4015x over previous
#include <cuda_runtime.h>
#include <cuda_fp16.h>
#include <cstdint>
#include <math.h>

#define NN 50000
#define EE 200000

// ---------------- scratch (static device globals; allocation-free) ----------------
__device__ float g_bufA[(size_t)NN * 1024];
__device__ float g_bufB[(size_t)NN * 1024];
__device__ float g_deg[NN];
__device__ float g_dis[NN];
__device__ float g_norm[EE];
__device__ __half g_Ahi[(size_t)NN * 1024];
__device__ __half g_Alo[(size_t)NN * 1024];
__device__ __half g_Wh[1024 * 1024];
__device__ __half g_Wl[1024 * 1024];

// ================= PTX helpers (arch-generic: sm_80+) =================
__device__ __forceinline__ uint32_t smem_to_u32(const void* p) {
    uint32_t a;
    asm("{ .reg .u64 t; cvta.to.shared.u64 t, %1; cvt.u32.u64 %0, t; }" : "=r"(a) : "l"(p));
    return a;
}
#define CP_ASYNC16(dst, src) \
    asm volatile("cp.async.cg.shared.global [%0], [%1], 16;" :: "r"(dst), "l"(src))
#define CP_COMMIT() asm volatile("cp.async.commit_group;" ::: "memory")
#define CP_WAIT(n)  asm volatile("cp.async.wait_group %0;" :: "n"(n) : "memory")
#define LDSM_X4(r0, r1, r2, r3, addr) \
    asm volatile("ldmatrix.sync.aligned.m8n8.x4.shared.b16 {%0,%1,%2,%3}, [%4];" \
        : "=r"(r0), "=r"(r1), "=r"(r2), "=r"(r3) : "r"(addr))
#define MMA_16816(c, a, b) \
    asm volatile("mma.sync.aligned.m16n8k16.row.col.f32.f16.f16.f32 " \
        "{%0,%1,%2,%3}, {%4,%5,%6,%7}, {%8,%9}, {%0,%1,%2,%3};" \
        : "+f"((c)[0]), "+f"((c)[1]), "+f"((c)[2]), "+f"((c)[3]) \
        : "r"((a)[0]), "r"((a)[1]), "r"((a)[2]), "r"((a)[3]), "r"((b)[0]), "r"((b)[1]))

// ================= prep kernels =================
__global__ void k_deg_init(float* __restrict__ deg) {
    int i = blockIdx.x * blockDim.x + threadIdx.x;
    if (i < NN) deg[i] = 1.0f;
}
__global__ void k_deg_edges(const int* __restrict__ col, float* __restrict__ deg) {
    int e = blockIdx.x * blockDim.x + threadIdx.x;
    if (e < EE) atomicAdd(&deg[col[e]], 1.0f);
}
__global__ void k_dis(const float* __restrict__ deg, float* __restrict__ dis) {
    int i = blockIdx.x * blockDim.x + threadIdx.x;
    if (i < NN) dis[i] = rsqrtf(deg[i]);
}
__global__ void k_norm(const int* __restrict__ row, const int* __restrict__ col,
                       const float* __restrict__ dis, float* __restrict__ nrm) {
    int e = blockIdx.x * blockDim.x + threadIdx.x;
    if (e < EE) nrm[e] = dis[row[e]] * dis[col[e]];
}

// ================= aggregation =================
template <bool BIAS>
__global__ void k_selfloop(const float* __restrict__ h, float* __restrict__ t,
                           const float* __restrict__ dis, const float* __restrict__ bias,
                           int F) {
    int idx = blockIdx.x * blockDim.x + threadIdx.x;
    int total = NN * F;
    if (idx >= total) return;
    int i = idx / F;
    int f = idx - i * F;
    float d = dis[i];
    float v = d * d * h[idx];
    if (BIAS) v += bias[f];
    t[idx] = v;
}

template <int F>
__global__ void k_edge_agg(const float* __restrict__ h, float* __restrict__ t,
                           const int* __restrict__ row, const int* __restrict__ col,
                           const float* __restrict__ nrm) {
    int idx = blockIdx.x * blockDim.x + threadIdx.x;
    if (idx >= EE * F) return;
    int e = idx / F;
    int f = idx - e * F;
    atomicAdd(&t[col[e] * F + f], nrm[e] * h[row[e] * F + f]);
}

// ================= split-fp16 conversion =================
// hi = fp16(x), lo = fp16(x - hi). Optional fused relu on input.
template <bool RELU>
__global__ void k_split(const float4* __restrict__ X, ushort4* __restrict__ hi,
                        ushort4* __restrict__ lo, int total4) {
    int i = blockIdx.x * blockDim.x + threadIdx.x;
    if (i >= total4) return;
    float4 v = X[i];
    if (RELU) {
        v.x = fmaxf(v.x, 0.f); v.y = fmaxf(v.y, 0.f);
        v.z = fmaxf(v.z, 0.f); v.w = fmaxf(v.w, 0.f);
    }
    __half h0 = __float2half(v.x), h1 = __float2half(v.y);
    __half h2 = __float2half(v.z), h3 = __float2half(v.w);
    __half l0 = __float2half(v.x - __half2float(h0));
    __half l1 = __float2half(v.y - __half2float(h1));
    __half l2 = __float2half(v.z - __half2float(h2));
    __half l3 = __float2half(v.w - __half2float(h3));
    ushort4 hv, lv;
    hv.x = __half_as_ushort(h0); hv.y = __half_as_ushort(h1);
    hv.z = __half_as_ushort(h2); hv.w = __half_as_ushort(h3);
    lv.x = __half_as_ushort(l0); lv.y = __half_as_ushort(l1);
    lv.z = __half_as_ushort(l2); lv.w = __half_as_ushort(l3);
    hi[i] = hv; lo[i] = lv;
}

// W [K,N] fp32 -> Wh/Wl [N,K] fp16 (transpose + split)
__global__ void k_wsplit(const float* __restrict__ W, __half* __restrict__ Wh,
                         __half* __restrict__ Wl, int K, int N) {
    int idx = blockIdx.x * blockDim.x + threadIdx.x;
    if (idx >= N * K) return;
    int n = idx / K;
    int k = idx - n * K;
    float v = W[(size_t)k * N + n];
    __half h = __float2half(v);
    Wh[idx] = h;
    Wl[idx] = __float2half(v - __half2float(h));
}

// ================= mma.sync split-fp16 GEMM =================
// C = AhWh + AlWh + AhWl  (drops only AlWl ~ 2^-22)
// Wh/Wl are [N,K] row-major = B col-major.
// CTA 128x128, BK=32, 8 warps (2m x 4n), each warp 64x32 via m16n8k16.
#define MG_STAGE 10240               // 128 rows x 80B (40 halves, padded)
#define MG_RSTR 80                   // smem row stride bytes

__device__ __forceinline__ void mg_load(const __half* __restrict__ Ap,
                                        const __half* __restrict__ Bp,
                                        int M, int K, int bm, int bn, int koff,
                                        uint32_t aDst, uint32_t bDst, int tid) {
    #pragma unroll
    for (int t = 0; t < 2; t++) {
        int idx = tid + t * 256;
        int r = idx >> 2, ch = idx & 3;
        int gr = bm + r;
        if (gr >= M) gr = M - 1;
        CP_ASYNC16(aDst + r * MG_RSTR + ch * 16,
                   (const void*)(Ap + (size_t)gr * K + koff + ch * 8));
    }
    #pragma unroll
    for (int t = 0; t < 2; t++) {
        int idx = tid + t * 256;
        int r = idx >> 2, ch = idx & 3;
        CP_ASYNC16(bDst + r * MG_RSTR + ch * 16,
                   (const void*)(Bp + (size_t)(bn + r) * K + koff + ch * 8));
    }
    CP_COMMIT();
}

template <bool BIAS_RELU>
__global__ void __launch_bounds__(256) k_mma_gemm(
    const __half* __restrict__ Ahi, const __half* __restrict__ Alo,
    const __half* __restrict__ Bhi, const __half* __restrict__ Blo,
    const float* __restrict__ bias,
    float* __restrict__ C, int M, int N, int K) {
    __shared__ __align__(16) __half sm[4 * 128 * 40];   // [A0][A1][B0][B1], 40 KB
    const uint32_t sbase = smem_to_u32(sm);
    const int tid = threadIdx.x;
    const int lane = tid & 31;
    const int wid = tid >> 5;
    const int wm = (wid & 1) * 64;
    const int wn = (wid >> 1) * 32;
    const int bm = blockIdx.y * 128;
    const int bn = blockIdx.x * 128;

    const int CK = K / 32;
    const int CT = 3 * CK;           // pass 0: AhWh, 1: AlWh, 2: AhWl

    float acc[4][4][4];
    #pragma unroll
    for (int i = 0; i < 4; i++)
        #pragma unroll
        for (int j = 0; j < 4; j++)
            #pragma unroll
            for (int q = 0; q < 4; q++) acc[i][j][q] = 0.f;

    mg_load(Ahi, Bhi, M, K, bm, bn, 0, sbase, sbase + 2 * MG_STAGE, tid);

    for (int c = 0; c < CT; c++) {
        const int s = c & 1;
        if (c + 1 < CT) {
            const int cn = c + 1;
            const int p = cn / CK;
            const int koff = (cn - p * CK) * 32;
            const __half* Ap = (p == 1) ? Alo : Ahi;
            const __half* Bp = (p == 2) ? Blo : Bhi;
            mg_load(Ap, Bp, M, K, bm, bn, koff,
                    sbase + (s ^ 1) * MG_STAGE, sbase + (2 + (s ^ 1)) * MG_STAGE, tid);
            CP_WAIT(1);
        } else {
            CP_WAIT(0);
        }
        __syncthreads();

        const uint32_t aBase = sbase + s * MG_STAGE;
        const uint32_t bBase = sbase + (2 + s) * MG_STAGE;
        #pragma unroll
        for (int kk = 0; kk < 32; kk += 16) {
            uint32_t a[4][4];
            #pragma unroll
            for (int mi = 0; mi < 4; mi++) {
                int row = wm + mi * 16 + (lane & 15);
                int colb = (kk + ((lane >> 4) << 3)) * 2;
                LDSM_X4(a[mi][0], a[mi][1], a[mi][2], a[mi][3],
                        aBase + row * MG_RSTR + colb);
            }
            uint32_t b[4][2];
            #pragma unroll
            for (int nb = 0; nb < 2; nb++) {
                int n = wn + nb * 16 + (lane & 7) + ((lane >> 4) << 3);
                int colb = (kk + (((lane >> 3) & 1) << 3)) * 2;
                LDSM_X4(b[2 * nb][0], b[2 * nb][1], b[2 * nb + 1][0], b[2 * nb + 1][1],
                        bBase + n * MG_RSTR + colb);
            }
            #pragma unroll
            for (int mi = 0; mi < 4; mi++)
                #pragma unroll
                for (int nj = 0; nj < 4; nj++)
                    MMA_16816(acc[mi][nj], a[mi], b[nj]);
        }
        __syncthreads();
    }

    // epilogue
    #pragma unroll
    for (int mi = 0; mi < 4; mi++) {
        int r0 = bm + wm + mi * 16 + (lane >> 2);
        #pragma unroll
        for (int nj = 0; nj < 4; nj++) {
            int cn = bn + wn + nj * 8 + (lane & 3) * 2;
            float2 v0, v1;
            v0.x = acc[mi][nj][0]; v0.y = acc[mi][nj][1];
            v1.x = acc[mi][nj][2]; v1.y = acc[mi][nj][3];
            if (BIAS_RELU) {
                float b0 = bias[cn], b1 = bias[cn + 1];
                v0.x = fmaxf(v0.x + b0, 0.f); v0.y = fmaxf(v0.y + b1, 0.f);
                v1.x = fmaxf(v1.x + b0, 0.f); v1.y = fmaxf(v1.y + b1, 0.f);
            }
            if (r0 < M)     *(float2*)(C + (size_t)r0 * N + cn) = v0;
            if (r0 + 8 < M) *(float2*)(C + (size_t)(r0 + 8) * N + cn) = v1;
        }
    }
}

// ================= SIMT GEMM (small layers L1-L3) =================
template <bool RELU, bool BIAS>
__global__ void __launch_bounds__(256) k_gemm(
    const float* __restrict__ A, const float* __restrict__ B,
    const float* __restrict__ bias, float* __restrict__ C,
    int M, int N, int K) {
    constexpr int BMx = 128, BNx = 64, BK = 16, TM = 8, TN = 4;
    constexpr int AST = BMx + 4;
    __shared__ float As[BK * AST];
    __shared__ float Bs[BK * BNx];
    const int tid = threadIdx.x;
    const int bm = blockIdx.y * BMx;
    const int bn = blockIdx.x * BNx;
    const int tx = tid & 15;
    const int ty = tid >> 4;
    const int ar = tid >> 2;
    const int ac = (tid & 3) * 4;
    const int br = tid >> 4;
    const int bc = (tid & 15) * 4;
    float acc[TM][TN] = {};
    for (int kt = 0; kt < K; kt += BK) {
        #pragma unroll
        for (int i = 0; i < 2; i++) {
            int r = ar + i * 64;
            int gr = bm + r;
            float4 v = make_float4(0.f, 0.f, 0.f, 0.f);
            if (gr < M) v = *(const float4*)(A + (size_t)gr * K + kt + ac);
            As[(ac + 0) * AST + r] = v.x;
            As[(ac + 1) * AST + r] = v.y;
            As[(ac + 2) * AST + r] = v.z;
            As[(ac + 3) * AST + r] = v.w;
        }
        {
            float4 v = *(const float4*)(B + (size_t)(kt + br) * N + bn + bc);
            *(float4*)(Bs + br * BNx + bc) = v;
        }
        __syncthreads();
        #pragma unroll
        for (int k = 0; k < BK; k++) {
            float ra[TM], rb[TN];
            float4 a0 = *(const float4*)(As + k * AST + ty * TM);
            float4 a1 = *(const float4*)(As + k * AST + ty * TM + 4);
            ra[0] = a0.x; ra[1] = a0.y; ra[2] = a0.z; ra[3] = a0.w;
            ra[4] = a1.x; ra[5] = a1.y; ra[6] = a1.z; ra[7] = a1.w;
            float4 b0 = *(const float4*)(Bs + k * BNx + tx * TN);
            rb[0] = b0.x; rb[1] = b0.y; rb[2] = b0.z; rb[3] = b0.w;
            #pragma unroll
            for (int m = 0; m < TM; m++)
                #pragma unroll
                for (int n = 0; n < TN; n++)
                    acc[m][n] += ra[m] * rb[n];
        }
        __syncthreads();
    }
    float bv[TN] = {0.f, 0.f, 0.f, 0.f};
    if (BIAS) {
        float4 t = *(const float4*)(bias + bn + tx * TN);
        bv[0] = t.x; bv[1] = t.y; bv[2] = t.z; bv[3] = t.w;
    }
    #pragma unroll
    for (int m = 0; m < TM; m++) {
        int gr = bm + ty * TM + m;
        if (gr < M) {
            float4 o;
            o.x = acc[m][0] + bv[0];
            o.y = acc[m][1] + bv[1];
            o.z = acc[m][2] + bv[2];
            o.w = acc[m][3] + bv[3];
            if (RELU) {
                o.x = fmaxf(o.x, 0.f); o.y = fmaxf(o.y, 0.f);
                o.z = fmaxf(o.z, 0.f); o.w = fmaxf(o.w, 0.f);
            }
            *(float4*)(C + (size_t)gr * N + bn + tx * TN) = o;
        }
    }
}

// ---------------- layer-0 GEMM (K=3, Fout=64, bias+relu) ----------------
__global__ void k_l0_gemm(const float* __restrict__ t, const float* __restrict__ W,
                          const float* __restrict__ b, float* __restrict__ y) {
    int idx = blockIdx.x * blockDim.x + threadIdx.x;
    if (idx >= NN * 64) return;
    int i = idx >> 6;
    int j = idx & 63;
    float acc = b[j];
    acc += t[i * 3 + 0] * W[0 * 64 + j];
    acc += t[i * 3 + 1] * W[1 * 64 + j];
    acc += t[i * 3 + 2] * W[2 * 64 + j];
    y[idx] = fmaxf(acc, 0.f);
}

// ---------------- layer-7 GEMM (K=256, Fout=2) with fused input relu ----
__global__ void k_l7_gemm(const float* __restrict__ x, const float* __restrict__ W,
                          float* __restrict__ h) {
    int gwarp = (blockIdx.x * blockDim.x + threadIdx.x) >> 5;
    int lane = threadIdx.x & 31;
    if (gwarp >= NN) return;
    const float4* xr = (const float4*)(x + (size_t)gwarp * 256);
    float a0 = 0.f, a1 = 0.f;
    #pragma unroll
    for (int it = 0; it < 2; it++) {
        int c4 = lane + it * 32;
        float4 v = xr[c4];
        v.x = fmaxf(v.x, 0.f); v.y = fmaxf(v.y, 0.f);
        v.z = fmaxf(v.z, 0.f); v.w = fmaxf(v.w, 0.f);
        int k = c4 * 4;
        a0 += v.x * W[(k + 0) * 2 + 0] + v.y * W[(k + 1) * 2 + 0]
            + v.z * W[(k + 2) * 2 + 0] + v.w * W[(k + 3) * 2 + 0];
        a1 += v.x * W[(k + 0) * 2 + 1] + v.y * W[(k + 1) * 2 + 1]
            + v.z * W[(k + 2) * 2 + 1] + v.w * W[(k + 3) * 2 + 1];
    }
    #pragma unroll
    for (int off = 16; off > 0; off >>= 1) {
        a0 += __shfl_down_sync(0xFFFFFFFFu, a0, off);
        a1 += __shfl_down_sync(0xFFFFFFFFu, a1, off);
    }
    if (lane == 0) {
        h[gwarp * 2 + 0] = a0;
        h[gwarp * 2 + 1] = a1;
    }
}

// ================= host orchestration =================
static inline void launch_gemm(const float* A, const float* B, const float* bias,
                               float* C, int M, int Nc, int K, bool relu_bias) {
    dim3 grid(Nc / 64, (M + 127) / 128);
    if (relu_bias) k_gemm<true, true><<<grid, 256>>>(A, B, bias, C, M, Nc, K);
    else           k_gemm<false, false><<<grid, 256>>>(A, B, nullptr, C, M, Nc, K);
}

extern "C" void kernel_launch(void* const* d_in, const int* in_sizes, int n_in,
                              void* d_out, int out_size) {
    const float* x = (const float*)d_in[0];
    const int* ei  = (const int*)d_in[1];
    const int* row = ei;
    const int* col = ei + EE;
    const float* W[8];
    const float* b[8];
    for (int i = 0; i < 8; i++) {
        W[i] = (const float*)d_in[2 + 2 * i];
        b[i] = (const float*)d_in[3 + 2 * i];
    }
    float *bufA, *bufB, *deg, *dis, *nrm;
    __half *Ahi, *Alo, *Wh, *Wl;
    cudaGetSymbolAddress((void**)&bufA, g_bufA);
    cudaGetSymbolAddress((void**)&bufB, g_bufB);
    cudaGetSymbolAddress((void**)&deg,  g_deg);
    cudaGetSymbolAddress((void**)&dis,  g_dis);
    cudaGetSymbolAddress((void**)&nrm,  g_norm);
    cudaGetSymbolAddress((void**)&Ahi,  g_Ahi);
    cudaGetSymbolAddress((void**)&Alo,  g_Alo);
    cudaGetSymbolAddress((void**)&Wh,   g_Wh);
    cudaGetSymbolAddress((void**)&Wl,   g_Wl);
    float* out = (float*)d_out;

    // ---- normalization prep ----
    k_deg_init<<<(NN + 255) / 256, 256>>>(deg);
    k_deg_edges<<<(EE + 255) / 256, 256>>>(col, deg);
    k_dis<<<(NN + 255) / 256, 256>>>(deg, dis);
    k_norm<<<(EE + 255) / 256, 256>>>(row, col, dis, nrm);

    // ---- L0: 3 -> 64 ----
    k_selfloop<false><<<(NN * 3 + 255) / 256, 256>>>(x, bufA, dis, nullptr, 3);
    k_edge_agg<3><<<(EE * 3 + 255) / 256, 256>>>(x, bufA, row, col, nrm);
    k_l0_gemm<<<(NN * 64 + 255) / 256, 256>>>(bufA, W[0], b[0], bufB);

    // ---- L1-L3 (SIMT fp32) ----
    k_selfloop<false><<<(NN * 64 + 255) / 256, 256>>>(bufB, bufA, dis, nullptr, 64);
    k_edge_agg<64><<<(EE * 64 + 255) / 256, 256>>>(bufB, bufA, row, col, nrm);
    launch_gemm(bufA, W[1], b[1], bufB, NN, 64, 64, true);

    k_selfloop<false><<<(NN * 64 + 255) / 256, 256>>>(bufB, bufA, dis, nullptr, 64);
    k_edge_agg<64><<<(EE * 64 + 255) / 256, 256>>>(bufB, bufA, row, col, nrm);
    launch_gemm(bufA, W[2], b[2], bufB, NN, 64, 64, true);

    k_selfloop<false><<<(NN * 64 + 255) / 256, 256>>>(bufB, bufA, dis, nullptr, 64);
    k_edge_agg<64><<<(EE * 64 + 255) / 256, 256>>>(bufB, bufA, row, col, nrm);
    launch_gemm(bufA, W[3], b[3], bufB, NN, 128, 64, true);

    // ---- L4: 128 -> 1024 (mma, bias+relu fused) ----
    k_selfloop<false><<<(NN * 128 + 255) / 256, 256>>>(bufB, bufA, dis, nullptr, 128);
    k_edge_agg<128><<<(EE * 128 + 255) / 256, 256>>>(bufB, bufA, row, col, nrm);
    k_split<false><<<(NN * 128 / 4 + 255) / 256, 256>>>((const float4*)bufA, (ushort4*)Ahi, (ushort4*)Alo, NN * 128 / 4);
    k_wsplit<<<(1024 * 128 + 255) / 256, 256>>>(W[4], Wh, Wl, 128, 1024);
    {
        dim3 grid(1024 / 128, (NN + 127) / 128);
        k_mma_gemm<true><<<grid, 256>>>(Ahi, Alo, Wh, Wl, b[4], bufB, NN, 1024, 128);
    }

    // ---- L5: 1024 -> 512 (mma; bias in selfloop; relu folded into L6 split) ----
    k_split<false><<<(NN * 1024 / 4 + 255) / 256, 256>>>((const float4*)bufB, (ushort4*)Ahi, (ushort4*)Alo, NN * 1024 / 4);
    k_wsplit<<<(512 * 1024 + 255) / 256, 256>>>(W[5], Wh, Wl, 1024, 512);
    {
        dim3 grid(512 / 128, (NN + 127) / 128);
        k_mma_gemm<false><<<grid, 256>>>(Ahi, Alo, Wh, Wl, nullptr, bufA, NN, 512, 1024);
    }
    k_selfloop<true><<<(NN * 512 + 255) / 256, 256>>>(bufA, bufB, dis, b[5], 512);
    k_edge_agg<512><<<(EE * 512 + 255) / 256, 256>>>(bufA, bufB, row, col, nrm);

    // ---- L6: 512 -> 256 (mma; relu fused into split; bias in selfloop) ----
    k_split<true><<<(NN * 512 / 4 + 255) / 256, 256>>>((const float4*)bufB, (ushort4*)Ahi, (ushort4*)Alo, NN * 512 / 4);
    k_wsplit<<<(256 * 512 + 255) / 256, 256>>>(W[6], Wh, Wl, 512, 256);
    {
        dim3 grid(256 / 128, (NN + 127) / 128);
        k_mma_gemm<false><<<grid, 256>>>(Ahi, Alo, Wh, Wl, nullptr, bufA, NN, 256, 512);
    }
    k_selfloop<true><<<(NN * 256 + 255) / 256, 256>>>(bufA, bufB, dis, b[6], 256);
    k_edge_agg<256><<<(EE * 256 + 255) / 256, 256>>>(bufA, bufB, row, col, nrm);

    // ---- L7: 256 -> 2 (relu fused into gemm load) ----
    k_l7_gemm<<<(NN * 32 + 255) / 256, 256>>>(bufB, W[7], bufA);
    k_selfloop<true><<<(NN * 2 + 255) / 256, 256>>>(bufA, out, dis, b[7], 2);
    k_edge_agg<2><<<(EE * 2 + 255) / 256, 256>>>(bufA, out, row, col, nrm);
}

// round 8
// speedup vs baseline: 2.2644x; 1.6158x over previous
#include <cuda_runtime.h>
#include <cuda_fp16.h>
#include <cstdint>
#include <math.h>

#define NN 50000
#define EE 200000
#define SCAN_BS 512
#define SCAN_NB 98          // ceil(NN/512)

// ---------------- scratch (static device globals; allocation-free) ----------------
__device__ float g_bufA[(size_t)NN * 1024];
__device__ float g_bufB[(size_t)NN * 1024];
__device__ __half g_Ahi[(size_t)NN * 1024];
__device__ __half g_Alo[(size_t)NN * 1024];
__device__ __half g_Bhi[(size_t)NN * 1024];
__device__ __half g_Blo[(size_t)NN * 1024];
__device__ __half g_Wh[1024 * 1024];
__device__ __half g_Wl[1024 * 1024];
__device__ int   g_cnt[NN];
__device__ int   g_cur[NN];
__device__ int   g_off[NN + 1];
__device__ int   g_bsum[SCAN_NB];
__device__ float g_dis[NN];
__device__ int   g_src[EE];
__device__ float g_enrm[EE];

// ================= PTX helpers (arch-generic: sm_80+) =================
__device__ __forceinline__ uint32_t smem_to_u32(const void* p) {
    uint32_t a;
    asm("{ .reg .u64 t; cvta.to.shared.u64 t, %1; cvt.u32.u64 %0, t; }" : "=r"(a) : "l"(p));
    return a;
}
#define CP_ASYNC16(dst, src) \
    asm volatile("cp.async.cg.shared.global [%0], [%1], 16;" :: "r"(dst), "l"(src))
#define CP_COMMIT() asm volatile("cp.async.commit_group;" ::: "memory")
#define CP_WAIT(n)  asm volatile("cp.async.wait_group %0;" :: "n"(n) : "memory")
#define LDSM_X4(r0, r1, r2, r3, addr) \
    asm volatile("ldmatrix.sync.aligned.m8n8.x4.shared.b16 {%0,%1,%2,%3}, [%4];" \
        : "=r"(r0), "=r"(r1), "=r"(r2), "=r"(r3) : "r"(addr))
#define MMA_16816(c, a, b) \
    asm volatile("mma.sync.aligned.m16n8k16.row.col.f32.f16.f16.f32 " \
        "{%0,%1,%2,%3}, {%4,%5,%6,%7}, {%8,%9}, {%0,%1,%2,%3};" \
        : "+f"((c)[0]), "+f"((c)[1]), "+f"((c)[2]), "+f"((c)[3]) \
        : "r"((a)[0]), "r"((a)[1]), "r"((a)[2]), "r"((a)[3]), "r"((b)[0]), "r"((b)[1]))

// ================= CSR build =================
__global__ void k_zero2(int* __restrict__ a, int* __restrict__ b) {
    int i = blockIdx.x * blockDim.x + threadIdx.x;
    if (i < NN) { a[i] = 0; b[i] = 0; }
}
__global__ void k_cnt(const int* __restrict__ col, int* __restrict__ cnt) {
    int e = blockIdx.x * blockDim.x + threadIdx.x;
    if (e < EE) atomicAdd(&cnt[col[e]], 1);
}
__global__ void k_scan1(const int* __restrict__ cnt, int* __restrict__ off,
                        int* __restrict__ bsum) {
    __shared__ int sh[SCAN_BS];
    int tid = threadIdx.x;
    int i = blockIdx.x * SCAN_BS + tid;
    int v = (i < NN) ? cnt[i] : 0;
    sh[tid] = v;
    __syncthreads();
    #pragma unroll
    for (int d = 1; d < SCAN_BS; d <<= 1) {
        int t = (tid >= d) ? sh[tid - d] : 0;
        __syncthreads();
        sh[tid] += t;
        __syncthreads();
    }
    if (i < NN) off[i] = sh[tid] - v;          // exclusive
    if (tid == SCAN_BS - 1) bsum[blockIdx.x] = sh[tid];
}
__global__ void k_scan2(int* __restrict__ bsum) {
    __shared__ int sh[128];
    int tid = threadIdx.x;
    int v = (tid < SCAN_NB) ? bsum[tid] : 0;
    sh[tid] = v;
    __syncthreads();
    #pragma unroll
    for (int d = 1; d < 128; d <<= 1) {
        int t = (tid >= d) ? sh[tid - d] : 0;
        __syncthreads();
        sh[tid] += t;
        __syncthreads();
    }
    if (tid < SCAN_NB) bsum[tid] = sh[tid] - v;  // exclusive
}
__global__ void k_scan3(int* __restrict__ off, const int* __restrict__ bsum) {
    int i = blockIdx.x * blockDim.x + threadIdx.x;
    if (i < NN) off[i] += bsum[i / SCAN_BS];
    if (i == 0) off[NN] = EE;
}
__global__ void k_disk(const int* __restrict__ cnt, float* __restrict__ dis) {
    int i = blockIdx.x * blockDim.x + threadIdx.x;
    if (i < NN) dis[i] = rsqrtf((float)(cnt[i] + 1));
}
__global__ void k_fill(const int* __restrict__ row, const int* __restrict__ col,
                       const float* __restrict__ dis, const int* __restrict__ off,
                       int* __restrict__ cur, int* __restrict__ src,
                       float* __restrict__ enrm) {
    int e = blockIdx.x * blockDim.x + threadIdx.x;
    if (e >= EE) return;
    int r = row[e], c = col[e];
    int pos = off[c] + atomicAdd(&cur[c], 1);
    src[pos] = r;
    enrm[pos] = dis[r] * dis[c];
}

// ================= fused CSR gather aggregation =================
// out[i] = (bias +) [relu] ( dis[i]^2 * h[i] + sum_{e->i} enrm_e * h[src_e] )
// SPLIT: write fp16 hi/lo pair buffers instead of fp32.
template <int F, bool BIAS, bool RELU, bool SPLIT>
__global__ void __launch_bounds__(256) k_gather4(
    const float4* __restrict__ h, const int* __restrict__ off,
    const int* __restrict__ src, const float* __restrict__ enrm,
    const float* __restrict__ dis, const float* __restrict__ bias,
    float4* __restrict__ outf, __half2* __restrict__ ohi, __half2* __restrict__ olo) {
    constexpr int FV = F / 4;
    int idx = blockIdx.x * blockDim.x + threadIdx.x;
    if (idx >= NN * FV) return;
    int i = idx / FV;
    int f4 = idx - i * FV;
    float d = dis[i];
    float s = d * d;
    float4 v = h[(size_t)i * FV + f4];
    float4 acc;
    acc.x = s * v.x; acc.y = s * v.y; acc.z = s * v.z; acc.w = s * v.w;
    int p0 = off[i], p1 = off[i + 1];
    for (int p = p0; p < p1; p++) {
        int sn = src[p];
        float w = enrm[p];
        float4 u = h[(size_t)sn * FV + f4];
        acc.x += w * u.x; acc.y += w * u.y; acc.z += w * u.z; acc.w += w * u.w;
    }
    if (BIAS) {
        const float4 bv = *(const float4*)(bias + f4 * 4);
        acc.x += bv.x; acc.y += bv.y; acc.z += bv.z; acc.w += bv.w;
    }
    if (RELU) {
        acc.x = fmaxf(acc.x, 0.f); acc.y = fmaxf(acc.y, 0.f);
        acc.z = fmaxf(acc.z, 0.f); acc.w = fmaxf(acc.w, 0.f);
    }
    if (SPLIT) {
        __half hx = __float2half(acc.x), hy = __float2half(acc.y);
        __half hz = __float2half(acc.z), hw = __float2half(acc.w);
        __half lx = __float2half(acc.x - __half2float(hx));
        __half ly = __float2half(acc.y - __half2float(hy));
        __half lz = __float2half(acc.z - __half2float(hz));
        __half lw = __float2half(acc.w - __half2float(hw));
        ohi[(size_t)idx * 2 + 0] = __halves2half2(hx, hy);
        ohi[(size_t)idx * 2 + 1] = __halves2half2(hz, hw);
        olo[(size_t)idx * 2 + 0] = __halves2half2(lx, ly);
        olo[(size_t)idx * 2 + 1] = __halves2half2(lz, lw);
    } else {
        outf[idx] = acc;
    }
}

// scalar variant for F=3 and F=2
template <int F, bool BIAS>
__global__ void k_gather1(const float* __restrict__ h, const int* __restrict__ off,
                          const int* __restrict__ src, const float* __restrict__ enrm,
                          const float* __restrict__ dis, const float* __restrict__ bias,
                          float* __restrict__ outf) {
    int idx = blockIdx.x * blockDim.x + threadIdx.x;
    if (idx >= NN * F) return;
    int i = idx / F;
    int f = idx - i * F;
    float d = dis[i];
    float acc = d * d * h[(size_t)i * F + f];
    int p0 = off[i], p1 = off[i + 1];
    for (int p = p0; p < p1; p++)
        acc += enrm[p] * h[(size_t)src[p] * F + f];
    if (BIAS) acc += bias[f];
    outf[idx] = acc;
}

// ================= split-fp16 weight transpose =================
// W [K,N] fp32 -> Wh/Wl [N,K] fp16
__global__ void k_wsplit(const float* __restrict__ W, __half* __restrict__ Wh,
                         __half* __restrict__ Wl, int K, int N) {
    int idx = blockIdx.x * blockDim.x + threadIdx.x;
    if (idx >= N * K) return;
    int n = idx / K;
    int k = idx - n * K;
    float v = W[(size_t)k * N + n];
    __half h = __float2half(v);
    Wh[idx] = h;
    Wl[idx] = __float2half(v - __half2float(h));
}

// ================= mma.sync split-fp16 GEMM =================
// C = AhWh + AlWh + AhWl   (Wh/Wl are [N,K] = B col-major)
// CTA 128x128, BK=32, 8 warps (2m x 4n). Optional bias+relu; optional split-fp16 output.
#define MG_STAGE 10240               // 128 rows x 80B (padded)
#define MG_RSTR 80

__device__ __forceinline__ void mg_load(const __half* __restrict__ Ap,
                                        const __half* __restrict__ Bp,
                                        int M, int K, int bm, int bn, int koff,
                                        uint32_t aDst, uint32_t bDst, int tid) {
    #pragma unroll
    for (int t = 0; t < 2; t++) {
        int idx = tid + t * 256;
        int r = idx >> 2, ch = idx & 3;
        int gr = bm + r;
        if (gr >= M) gr = M - 1;
        CP_ASYNC16(aDst + r * MG_RSTR + ch * 16,
                   (const void*)(Ap + (size_t)gr * K + koff + ch * 8));
    }
    #pragma unroll
    for (int t = 0; t < 2; t++) {
        int idx = tid + t * 256;
        int r = idx >> 2, ch = idx & 3;
        CP_ASYNC16(bDst + r * MG_RSTR + ch * 16,
                   (const void*)(Bp + (size_t)(bn + r) * K + koff + ch * 8));
    }
    CP_COMMIT();
}

template <bool BIAS_RELU, bool SPLIT>
__global__ void __launch_bounds__(256) k_mma_gemm(
    const __half* __restrict__ Ahi, const __half* __restrict__ Alo,
    const __half* __restrict__ Bhi, const __half* __restrict__ Blo,
    const float* __restrict__ bias, float* __restrict__ Cf,
    __half2* __restrict__ Chi, __half2* __restrict__ Clo,
    int M, int N, int K) {
    __shared__ __align__(16) __half sm[4 * 128 * 40];
    const uint32_t sbase = smem_to_u32(sm);
    const int tid = threadIdx.x;
    const int lane = tid & 31;
    const int wid = tid >> 5;
    const int wm = (wid & 1) * 64;
    const int wn = (wid >> 1) * 32;
    const int bm = blockIdx.y * 128;
    const int bn = blockIdx.x * 128;

    const int CK = K / 32;
    const int CT = 3 * CK;

    float acc[4][4][4];
    #pragma unroll
    for (int i = 0; i < 4; i++)
        #pragma unroll
        for (int j = 0; j < 4; j++)
            #pragma unroll
            for (int q = 0; q < 4; q++) acc[i][j][q] = 0.f;

    mg_load(Ahi, Bhi, M, K, bm, bn, 0, sbase, sbase + 2 * MG_STAGE, tid);

    for (int c = 0; c < CT; c++) {
        const int s = c & 1;
        if (c + 1 < CT) {
            const int cn = c + 1;
            const int p = cn / CK;
            const int koff = (cn - p * CK) * 32;
            const __half* Ap = (p == 1) ? Alo : Ahi;
            const __half* Bp = (p == 2) ? Blo : Bhi;
            mg_load(Ap, Bp, M, K, bm, bn, koff,
                    sbase + (s ^ 1) * MG_STAGE, sbase + (2 + (s ^ 1)) * MG_STAGE, tid);
            CP_WAIT(1);
        } else {
            CP_WAIT(0);
        }
        __syncthreads();

        const uint32_t aBase = sbase + s * MG_STAGE;
        const uint32_t bBase = sbase + (2 + s) * MG_STAGE;
        #pragma unroll
        for (int kk = 0; kk < 32; kk += 16) {
            uint32_t a[4][4];
            #pragma unroll
            for (int mi = 0; mi < 4; mi++) {
                int r = wm + mi * 16 + (lane & 15);
                int colb = (kk + ((lane >> 4) << 3)) * 2;
                LDSM_X4(a[mi][0], a[mi][1], a[mi][2], a[mi][3],
                        aBase + r * MG_RSTR + colb);
            }
            uint32_t b[4][2];
            #pragma unroll
            for (int nb = 0; nb < 2; nb++) {
                int n = wn + nb * 16 + (lane & 7) + ((lane >> 4) << 3);
                int colb = (kk + (((lane >> 3) & 1) << 3)) * 2;
                LDSM_X4(b[2 * nb][0], b[2 * nb][1], b[2 * nb + 1][0], b[2 * nb + 1][1],
                        bBase + n * MG_RSTR + colb);
            }
            #pragma unroll
            for (int mi = 0; mi < 4; mi++)
                #pragma unroll
                for (int nj = 0; nj < 4; nj++)
                    MMA_16816(acc[mi][nj], a[mi], b[nj]);
        }
        __syncthreads();
    }

    // epilogue
    #pragma unroll
    for (int mi = 0; mi < 4; mi++) {
        int r0 = bm + wm + mi * 16 + (lane >> 2);
        #pragma unroll
        for (int nj = 0; nj < 4; nj++) {
            int cn = bn + wn + nj * 8 + (lane & 3) * 2;
            float2 v0, v1;
            v0.x = acc[mi][nj][0]; v0.y = acc[mi][nj][1];
            v1.x = acc[mi][nj][2]; v1.y = acc[mi][nj][3];
            if (BIAS_RELU) {
                float b0 = bias[cn], b1 = bias[cn + 1];
                v0.x = fmaxf(v0.x + b0, 0.f); v0.y = fmaxf(v0.y + b1, 0.f);
                v1.x = fmaxf(v1.x + b0, 0.f); v1.y = fmaxf(v1.y + b1, 0.f);
            }
            if (SPLIT) {
                #pragma unroll
                for (int rr = 0; rr < 2; rr++) {
                    int r = r0 + rr * 8;
                    if (r < M) {
                        float2 v = rr ? v1 : v0;
                        __half hx = __float2half(v.x), hy = __float2half(v.y);
                        __half lx = __float2half(v.x - __half2float(hx));
                        __half ly = __float2half(v.y - __half2float(hy));
                        size_t o = ((size_t)r * N + cn) >> 1;
                        Chi[o] = __halves2half2(hx, hy);
                        Clo[o] = __halves2half2(lx, ly);
                    }
                }
            } else {
                if (r0 < M)     *(float2*)(Cf + (size_t)r0 * N + cn) = v0;
                if (r0 + 8 < M) *(float2*)(Cf + (size_t)(r0 + 8) * N + cn) = v1;
            }
        }
    }
}

// ================= SIMT GEMM (small layers L1-L3) =================
template <bool RELU, bool BIAS>
__global__ void __launch_bounds__(256) k_gemm(
    const float* __restrict__ A, const float* __restrict__ B,
    const float* __restrict__ bias, float* __restrict__ C,
    int M, int N, int K) {
    constexpr int BMx = 128, BNx = 64, BK = 16, TM = 8, TN = 4;
    constexpr int AST = BMx + 4;
    __shared__ float As[BK * AST];
    __shared__ float Bs[BK * BNx];
    const int tid = threadIdx.x;
    const int bm = blockIdx.y * BMx;
    const int bn = blockIdx.x * BNx;
    const int tx = tid & 15;
    const int ty = tid >> 4;
    const int ar = tid >> 2;
    const int ac = (tid & 3) * 4;
    const int br = tid >> 4;
    const int bc = (tid & 15) * 4;
    float acc[TM][TN] = {};
    for (int kt = 0; kt < K; kt += BK) {
        #pragma unroll
        for (int i = 0; i < 2; i++) {
            int r = ar + i * 64;
            int gr = bm + r;
            float4 v = make_float4(0.f, 0.f, 0.f, 0.f);
            if (gr < M) v = *(const float4*)(A + (size_t)gr * K + kt + ac);
            As[(ac + 0) * AST + r] = v.x;
            As[(ac + 1) * AST + r] = v.y;
            As[(ac + 2) * AST + r] = v.z;
            As[(ac + 3) * AST + r] = v.w;
        }
        {
            float4 v = *(const float4*)(B + (size_t)(kt + br) * N + bn + bc);
            *(float4*)(Bs + br * BNx + bc) = v;
        }
        __syncthreads();
        #pragma unroll
        for (int k = 0; k < BK; k++) {
            float ra[TM], rb[TN];
            float4 a0 = *(const float4*)(As + k * AST + ty * TM);
            float4 a1 = *(const float4*)(As + k * AST + ty * TM + 4);
            ra[0] = a0.x; ra[1] = a0.y; ra[2] = a0.z; ra[3] = a0.w;
            ra[4] = a1.x; ra[5] = a1.y; ra[6] = a1.z; ra[7] = a1.w;
            float4 b0 = *(const float4*)(Bs + k * BNx + tx * TN);
            rb[0] = b0.x; rb[1] = b0.y; rb[2] = b0.z; rb[3] = b0.w;
            #pragma unroll
            for (int m = 0; m < TM; m++)
                #pragma unroll
                for (int n = 0; n < TN; n++)
                    acc[m][n] += ra[m] * rb[n];
        }
        __syncthreads();
    }
    float bv[TN] = {0.f, 0.f, 0.f, 0.f};
    if (BIAS) {
        float4 t = *(const float4*)(bias + bn + tx * TN);
        bv[0] = t.x; bv[1] = t.y; bv[2] = t.z; bv[3] = t.w;
    }
    #pragma unroll
    for (int m = 0; m < TM; m++) {
        int gr = bm + ty * TM + m;
        if (gr < M) {
            float4 o;
            o.x = acc[m][0] + bv[0];
            o.y = acc[m][1] + bv[1];
            o.z = acc[m][2] + bv[2];
            o.w = acc[m][3] + bv[3];
            if (RELU) {
                o.x = fmaxf(o.x, 0.f); o.y = fmaxf(o.y, 0.f);
                o.z = fmaxf(o.z, 0.f); o.w = fmaxf(o.w, 0.f);
            }
            *(float4*)(C + (size_t)gr * N + bn + tx * TN) = o;
        }
    }
}

// ---------------- layer-0 GEMM (K=3, Fout=64, bias+relu) ----------------
__global__ void k_l0_gemm(const float* __restrict__ t, const float* __restrict__ W,
                          const float* __restrict__ b, float* __restrict__ y) {
    int idx = blockIdx.x * blockDim.x + threadIdx.x;
    if (idx >= NN * 64) return;
    int i = idx >> 6;
    int j = idx & 63;
    float acc = b[j];
    acc += t[i * 3 + 0] * W[0 * 64 + j];
    acc += t[i * 3 + 1] * W[1 * 64 + j];
    acc += t[i * 3 + 2] * W[2 * 64 + j];
    y[idx] = fmaxf(acc, 0.f);
}

// ---------------- layer-7 GEMM (K=256, Fout=2) with fused input relu ----
__global__ void k_l7_gemm(const float* __restrict__ x, const float* __restrict__ W,
                          float* __restrict__ h) {
    int gwarp = (blockIdx.x * blockDim.x + threadIdx.x) >> 5;
    int lane = threadIdx.x & 31;
    if (gwarp >= NN) return;
    const float4* xr = (const float4*)(x + (size_t)gwarp * 256);
    float a0 = 0.f, a1 = 0.f;
    #pragma unroll
    for (int it = 0; it < 2; it++) {
        int c4 = lane + it * 32;
        float4 v = xr[c4];
        v.x = fmaxf(v.x, 0.f); v.y = fmaxf(v.y, 0.f);
        v.z = fmaxf(v.z, 0.f); v.w = fmaxf(v.w, 0.f);
        int k = c4 * 4;
        a0 += v.x * W[(k + 0) * 2 + 0] + v.y * W[(k + 1) * 2 + 0]
            + v.z * W[(k + 2) * 2 + 0] + v.w * W[(k + 3) * 2 + 0];
        a1 += v.x * W[(k + 0) * 2 + 1] + v.y * W[(k + 1) * 2 + 1]
            + v.z * W[(k + 2) * 2 + 1] + v.w * W[(k + 3) * 2 + 1];
    }
    #pragma unroll
    for (int off = 16; off > 0; off >>= 1) {
        a0 += __shfl_down_sync(0xFFFFFFFFu, a0, off);
        a1 += __shfl_down_sync(0xFFFFFFFFu, a1, off);
    }
    if (lane == 0) {
        h[gwarp * 2 + 0] = a0;
        h[gwarp * 2 + 1] = a1;
    }
}

// ================= host orchestration =================
extern "C" void kernel_launch(void* const* d_in, const int* in_sizes, int n_in,
                              void* d_out, int out_size) {
    const float* x = (const float*)d_in[0];
    const int* ei  = (const int*)d_in[1];
    const int* row = ei;
    const int* col = ei + EE;
    const float* W[8];
    const float* b[8];
    for (int i = 0; i < 8; i++) {
        W[i] = (const float*)d_in[2 + 2 * i];
        b[i] = (const float*)d_in[3 + 2 * i];
    }
    float *bufA, *bufB, *dis, *enrm;
    __half *Ahi, *Alo, *Bhi, *Blo, *Wh, *Wl;
    int *cnt, *cur, *off, *bsum, *src;
    cudaGetSymbolAddress((void**)&bufA, g_bufA);
    cudaGetSymbolAddress((void**)&bufB, g_bufB);
    cudaGetSymbolAddress((void**)&Ahi,  g_Ahi);
    cudaGetSymbolAddress((void**)&Alo,  g_Alo);
    cudaGetSymbolAddress((void**)&Bhi,  g_Bhi);
    cudaGetSymbolAddress((void**)&Blo,  g_Blo);
    cudaGetSymbolAddress((void**)&Wh,   g_Wh);
    cudaGetSymbolAddress((void**)&Wl,   g_Wl);
    cudaGetSymbolAddress((void**)&cnt,  g_cnt);
    cudaGetSymbolAddress((void**)&cur,  g_cur);
    cudaGetSymbolAddress((void**)&off,  g_off);
    cudaGetSymbolAddress((void**)&bsum, g_bsum);
    cudaGetSymbolAddress((void**)&dis,  g_dis);
    cudaGetSymbolAddress((void**)&src,  g_src);
    cudaGetSymbolAddress((void**)&enrm, g_enrm);
    float* out = (float*)d_out;

    // ---- CSR build ----
    k_zero2<<<(NN + 255) / 256, 256>>>(cnt, cur);
    k_cnt<<<(EE + 255) / 256, 256>>>(col, cnt);
    k_scan1<<<SCAN_NB, SCAN_BS>>>(cnt, off, bsum);
    k_scan2<<<1, 128>>>(bsum);
    k_scan3<<<(NN + 255) / 256, 256>>>(off, bsum);
    k_disk<<<(NN + 255) / 256, 256>>>(cnt, dis);
    k_fill<<<(EE + 255) / 256, 256>>>(row, col, dis, off, cur, src, enrm);

    // ---- L0: 3 -> 64 ----
    k_gather1<3, false><<<(NN * 3 + 255) / 256, 256>>>(x, off, src, enrm, dis, nullptr, bufA);
    k_l0_gemm<<<(NN * 64 + 255) / 256, 256>>>(bufA, W[0], b[0], bufB);

    // ---- L1-L3 (SIMT fp32) ----
    k_gather4<64, false, false, false><<<(NN * 16 + 255) / 256, 256>>>(
        (const float4*)bufB, off, src, enrm, dis, nullptr, (float4*)bufA, nullptr, nullptr);
    k_gemm<true, true><<<dim3(1, (NN + 127) / 128), 256>>>(bufA, W[1], b[1], bufB, NN, 64, 64);

    k_gather4<64, false, false, false><<<(NN * 16 + 255) / 256, 256>>>(
        (const float4*)bufB, off, src, enrm, dis, nullptr, (float4*)bufA, nullptr, nullptr);
    k_gemm<true, true><<<dim3(1, (NN + 127) / 128), 256>>>(bufA, W[2], b[2], bufB, NN, 64, 64);

    k_gather4<64, false, false, false><<<(NN * 16 + 255) / 256, 256>>>(
        (const float4*)bufB, off, src, enrm, dis, nullptr, (float4*)bufA, nullptr, nullptr);
    k_gemm<true, true><<<dim3(2, (NN + 127) / 128), 256>>>(bufA, W[3], b[3], bufB, NN, 128, 64);

    // ---- L4: 128 -> 1024 (gather->split, mma with bias+relu, split output) ----
    k_gather4<128, false, false, true><<<(NN * 32 + 255) / 256, 256>>>(
        (const float4*)bufB, off, src, enrm, dis, nullptr, nullptr, (__half2*)Ahi, (__half2*)Alo);
    k_wsplit<<<(1024 * 128 + 255) / 256, 256>>>(W[4], Wh, Wl, 128, 1024);
    k_mma_gemm<true, true><<<dim3(8, (NN + 127) / 128), 256>>>(
        Ahi, Alo, Wh, Wl, b[4], nullptr, (__half2*)Bhi, (__half2*)Blo, NN, 1024, 128);

    // ---- L5: 1024 -> 512 (mma fp32 out; gather fuses bias+relu+split) ----
    k_wsplit<<<(512 * 1024 + 255) / 256, 256>>>(W[5], Wh, Wl, 1024, 512);
    k_mma_gemm<false, false><<<dim3(4, (NN + 127) / 128), 256>>>(
        Bhi, Blo, Wh, Wl, nullptr, bufA, nullptr, nullptr, NN, 512, 1024);
    k_gather4<512, true, true, true><<<(NN * 128 + 255) / 256, 256>>>(
        (const float4*)bufA, off, src, enrm, dis, b[5], nullptr, (__half2*)Ahi, (__half2*)Alo);

    // ---- L6: 512 -> 256 (mma fp32 out; gather fuses bias; relu in L7 load) ----
    k_wsplit<<<(256 * 512 + 255) / 256, 256>>>(W[6], Wh, Wl, 512, 256);
    k_mma_gemm<false, false><<<dim3(2, (NN + 127) / 128), 256>>>(
        Ahi, Alo, Wh, Wl, nullptr, bufB, nullptr, nullptr, NN, 256, 512);
    k_gather4<256, true, false, false><<<(NN * 64 + 255) / 256, 256>>>(
        (const float4*)bufB, off, src, enrm, dis, b[6], (float4*)bufA, nullptr, nullptr);

    // ---- L7: 256 -> 2 (relu fused into gemm load; gather fuses bias, writes d_out) ----
    k_l7_gemm<<<(NN * 32 + 255) / 256, 256>>>(bufA, W[7], bufB);
    k_gather1<2, true><<<(NN * 2 + 255) / 256, 256>>>(bufB, off, src, enrm, dis, b[7], out);
}

// round 9
// speedup vs baseline: 2.5245x; 1.1149x over previous
#include <cuda_runtime.h>
#include <cuda_fp16.h>
#include <cstdint>
#include <math.h>

#define NN 50000
#define EE 200000
#define SCAN_BS 512
#define SCAN_NB 98          // ceil(NN/512)

// ---------------- scratch (static device globals; allocation-free) ----------------
__device__ float g_bufA[(size_t)NN * 1024];
__device__ float g_bufB[(size_t)NN * 1024];
__device__ __half g_Ahi[(size_t)NN * 1024];
__device__ __half g_Alo[(size_t)NN * 1024];
__device__ __half g_Bhi[(size_t)NN * 1024];
__device__ __half g_Blo[(size_t)NN * 1024];
__device__ __half g_Wh[1024 * 1024];
__device__ __half g_Wl[1024 * 1024];
__device__ int   g_cnt[NN];
__device__ int   g_cur[NN];
__device__ int   g_off[NN + 1];
__device__ int   g_bsum[SCAN_NB];
__device__ float g_dis[NN];
__device__ int   g_src[EE];
__device__ float g_enrm[EE];

// ================= PTX helpers (arch-generic: sm_80+) =================
__device__ __forceinline__ uint32_t smem_to_u32(const void* p) {
    uint32_t a;
    asm("{ .reg .u64 t; cvta.to.shared.u64 t, %1; cvt.u32.u64 %0, t; }" : "=r"(a) : "l"(p));
    return a;
}
#define CP_ASYNC16(dst, src) \
    asm volatile("cp.async.cg.shared.global [%0], [%1], 16;" :: "r"(dst), "l"(src))
#define CP_COMMIT() asm volatile("cp.async.commit_group;" ::: "memory")
#define CP_WAIT(n)  asm volatile("cp.async.wait_group %0;" :: "n"(n) : "memory")
#define LDSM_X4(r0, r1, r2, r3, addr) \
    asm volatile("ldmatrix.sync.aligned.m8n8.x4.shared.b16 {%0,%1,%2,%3}, [%4];" \
        : "=r"(r0), "=r"(r1), "=r"(r2), "=r"(r3) : "r"(addr))
#define MMA_16816(c, a, b) \
    asm volatile("mma.sync.aligned.m16n8k16.row.col.f32.f16.f16.f32 " \
        "{%0,%1,%2,%3}, {%4,%5,%6,%7}, {%8,%9}, {%0,%1,%2,%3};" \
        : "+f"((c)[0]), "+f"((c)[1]), "+f"((c)[2]), "+f"((c)[3]) \
        : "r"((a)[0]), "r"((a)[1]), "r"((a)[2]), "r"((a)[3]), "r"((b)[0]), "r"((b)[1]))

// ================= CSR build =================
__global__ void k_zero2(int* __restrict__ a, int* __restrict__ b) {
    int i = blockIdx.x * blockDim.x + threadIdx.x;
    if (i < NN) { a[i] = 0; b[i] = 0; }
}
__global__ void k_cnt(const int* __restrict__ col, int* __restrict__ cnt) {
    int e = blockIdx.x * blockDim.x + threadIdx.x;
    if (e < EE) atomicAdd(&cnt[col[e]], 1);
}
__global__ void k_scan1(const int* __restrict__ cnt, int* __restrict__ off,
                        int* __restrict__ bsum) {
    __shared__ int sh[SCAN_BS];
    int tid = threadIdx.x;
    int i = blockIdx.x * SCAN_BS + tid;
    int v = (i < NN) ? cnt[i] : 0;
    sh[tid] = v;
    __syncthreads();
    #pragma unroll
    for (int d = 1; d < SCAN_BS; d <<= 1) {
        int t = (tid >= d) ? sh[tid - d] : 0;
        __syncthreads();
        sh[tid] += t;
        __syncthreads();
    }
    if (i < NN) off[i] = sh[tid] - v;          // exclusive
    if (tid == SCAN_BS - 1) bsum[blockIdx.x] = sh[tid];
}
__global__ void k_scan2(int* __restrict__ bsum) {
    __shared__ int sh[128];
    int tid = threadIdx.x;
    int v = (tid < SCAN_NB) ? bsum[tid] : 0;
    sh[tid] = v;
    __syncthreads();
    #pragma unroll
    for (int d = 1; d < 128; d <<= 1) {
        int t = (tid >= d) ? sh[tid - d] : 0;
        __syncthreads();
        sh[tid] += t;
        __syncthreads();
    }
    if (tid < SCAN_NB) bsum[tid] = sh[tid] - v;  // exclusive
}
__global__ void k_scan3(int* __restrict__ off, const int* __restrict__ bsum) {
    int i = blockIdx.x * blockDim.x + threadIdx.x;
    if (i < NN) off[i] += bsum[i / SCAN_BS];
    if (i == 0) off[NN] = EE;
}
__global__ void k_disk(const int* __restrict__ cnt, float* __restrict__ dis) {
    int i = blockIdx.x * blockDim.x + threadIdx.x;
    if (i < NN) dis[i] = rsqrtf((float)(cnt[i] + 1));
}
__global__ void k_fill(const int* __restrict__ row, const int* __restrict__ col,
                       const float* __restrict__ dis, const int* __restrict__ off,
                       int* __restrict__ cur, int* __restrict__ src,
                       float* __restrict__ enrm) {
    int e = blockIdx.x * blockDim.x + threadIdx.x;
    if (e >= EE) return;
    int r = row[e], c = col[e];
    int pos = off[c] + atomicAdd(&cur[c], 1);
    src[pos] = r;
    enrm[pos] = dis[r] * dis[c];
}

// ================= fused CSR gather aggregation =================
template <int F, bool BIAS, bool RELU, bool SPLIT>
__global__ void __launch_bounds__(256) k_gather4(
    const float4* __restrict__ h, const int* __restrict__ off,
    const int* __restrict__ src, const float* __restrict__ enrm,
    const float* __restrict__ dis, const float* __restrict__ bias,
    float4* __restrict__ outf, __half2* __restrict__ ohi, __half2* __restrict__ olo) {
    constexpr int FV = F / 4;
    int idx = blockIdx.x * blockDim.x + threadIdx.x;
    if (idx >= NN * FV) return;
    int i = idx / FV;
    int f4 = idx - i * FV;
    float d = dis[i];
    float s = d * d;
    float4 v = h[(size_t)i * FV + f4];
    float4 acc;
    acc.x = s * v.x; acc.y = s * v.y; acc.z = s * v.z; acc.w = s * v.w;
    int p0 = off[i], p1 = off[i + 1];
    for (int p = p0; p < p1; p++) {
        int sn = src[p];
        float w = enrm[p];
        float4 u = h[(size_t)sn * FV + f4];
        acc.x += w * u.x; acc.y += w * u.y; acc.z += w * u.z; acc.w += w * u.w;
    }
    if (BIAS) {
        const float4 bv = *(const float4*)(bias + f4 * 4);
        acc.x += bv.x; acc.y += bv.y; acc.z += bv.z; acc.w += bv.w;
    }
    if (RELU) {
        acc.x = fmaxf(acc.x, 0.f); acc.y = fmaxf(acc.y, 0.f);
        acc.z = fmaxf(acc.z, 0.f); acc.w = fmaxf(acc.w, 0.f);
    }
    if (SPLIT) {
        __half hx = __float2half(acc.x), hy = __float2half(acc.y);
        __half hz = __float2half(acc.z), hw = __float2half(acc.w);
        __half lx = __float2half(acc.x - __half2float(hx));
        __half ly = __float2half(acc.y - __half2float(hy));
        __half lz = __float2half(acc.z - __half2float(hz));
        __half lw = __float2half(acc.w - __half2float(hw));
        ohi[(size_t)idx * 2 + 0] = __halves2half2(hx, hy);
        ohi[(size_t)idx * 2 + 1] = __halves2half2(hz, hw);
        olo[(size_t)idx * 2 + 0] = __halves2half2(lx, ly);
        olo[(size_t)idx * 2 + 1] = __halves2half2(lz, lw);
    } else {
        outf[idx] = acc;
    }
}

// scalar variant for F=3 and F=2
template <int F, bool BIAS>
__global__ void k_gather1(const float* __restrict__ h, const int* __restrict__ off,
                          const int* __restrict__ src, const float* __restrict__ enrm,
                          const float* __restrict__ dis, const float* __restrict__ bias,
                          float* __restrict__ outf) {
    int idx = blockIdx.x * blockDim.x + threadIdx.x;
    if (idx >= NN * F) return;
    int i = idx / F;
    int f = idx - i * F;
    float d = dis[i];
    float acc = d * d * h[(size_t)i * F + f];
    int p0 = off[i], p1 = off[i + 1];
    for (int p = p0; p < p1; p++)
        acc += enrm[p] * h[(size_t)src[p] * F + f];
    if (BIAS) acc += bias[f];
    outf[idx] = acc;
}

// ================= split-fp16 weight transpose =================
__global__ void k_wsplit(const float* __restrict__ W, __half* __restrict__ Wh,
                         __half* __restrict__ Wl, int K, int N) {
    int idx = blockIdx.x * blockDim.x + threadIdx.x;
    if (idx >= N * K) return;
    int n = idx / K;
    int k = idx - n * K;
    float v = W[(size_t)k * N + n];
    __half h = __float2half(v);
    Wh[idx] = h;
    Wl[idx] = __float2half(v - __half2float(h));
}

// ================= fused-product mma.sync split-fp16 GEMM =================
// C = AhWh + AlWh + AhWl, all three products issued per K-chunk (single K sweep).
// CTA tile 128x256, BK=32, 8 warps (2m x 4n), warp tile 64x64.
// Stage layout (61440 B): [Ah 10240][Al 10240][Bh 20480][Bl 20480]; 2 stages.
#define MG_RSTR  80
#define MG_AT    10240
#define MG_BT    20480
#define MG_ST4   61440
#define MG_SMEM  (2 * MG_ST4)

__device__ __forceinline__ void mg_load4(
    const __half* __restrict__ Ah_, const __half* __restrict__ Al_,
    const __half* __restrict__ Bh_, const __half* __restrict__ Bl_,
    int M, int K, int bm, int bn, int koff, uint32_t st, int tid) {
    #pragma unroll
    for (int i = 0; i < 2; i++) {
        int idx = tid + i * 256;
        int r = idx >> 2, ch = idx & 3;
        int gr = bm + r;
        if (gr >= M) gr = M - 1;
        CP_ASYNC16(st + r * MG_RSTR + ch * 16,
                   (const void*)(Ah_ + (size_t)gr * K + koff + ch * 8));
    }
    #pragma unroll
    for (int i = 0; i < 2; i++) {
        int idx = tid + i * 256;
        int r = idx >> 2, ch = idx & 3;
        int gr = bm + r;
        if (gr >= M) gr = M - 1;
        CP_ASYNC16(st + MG_AT + r * MG_RSTR + ch * 16,
                   (const void*)(Al_ + (size_t)gr * K + koff + ch * 8));
    }
    #pragma unroll
    for (int i = 0; i < 4; i++) {
        int idx = tid + i * 256;
        int r = idx >> 2, ch = idx & 3;
        CP_ASYNC16(st + 2 * MG_AT + r * MG_RSTR + ch * 16,
                   (const void*)(Bh_ + (size_t)(bn + r) * K + koff + ch * 8));
    }
    #pragma unroll
    for (int i = 0; i < 4; i++) {
        int idx = tid + i * 256;
        int r = idx >> 2, ch = idx & 3;
        CP_ASYNC16(st + 2 * MG_AT + MG_BT + r * MG_RSTR + ch * 16,
                   (const void*)(Bl_ + (size_t)(bn + r) * K + koff + ch * 8));
    }
    CP_COMMIT();
}

template <bool BIAS_RELU, bool SPLIT>
__global__ void __launch_bounds__(256) k_mma_gemm(
    const __half* __restrict__ Ahi, const __half* __restrict__ Alo,
    const __half* __restrict__ Bhi, const __half* __restrict__ Blo,
    const float* __restrict__ bias, float* __restrict__ Cf,
    __half2* __restrict__ Chi, __half2* __restrict__ Clo,
    int M, int N, int K) {
    extern __shared__ __align__(16) char smx[];
    const uint32_t sbase = smem_to_u32(smx);
    const int tid = threadIdx.x;
    const int lane = tid & 31;
    const int wid = tid >> 5;
    const int wm = (wid & 1) * 64;
    const int wn = (wid >> 1) * 64;
    const int bm = blockIdx.y * 128;
    const int bn = blockIdx.x * 256;

    const int CK = K / 32;

    float acc[4][8][4];
    #pragma unroll
    for (int i = 0; i < 4; i++)
        #pragma unroll
        for (int j = 0; j < 8; j++)
            #pragma unroll
            for (int q = 0; q < 4; q++) acc[i][j][q] = 0.f;

    mg_load4(Ahi, Alo, Bhi, Blo, M, K, bm, bn, 0, sbase, tid);

    for (int c = 0; c < CK; c++) {
        const int s = c & 1;
        if (c + 1 < CK) {
            mg_load4(Ahi, Alo, Bhi, Blo, M, K, bm, bn, (c + 1) * 32,
                     sbase + (s ^ 1) * MG_ST4, tid);
            CP_WAIT(1);
        } else {
            CP_WAIT(0);
        }
        __syncthreads();

        const uint32_t base = sbase + s * MG_ST4;
        #pragma unroll
        for (int kk = 0; kk < 32; kk += 16) {
            uint32_t ah[4][4], al[4][4];
            #pragma unroll
            for (int mi = 0; mi < 4; mi++) {
                int r = wm + mi * 16 + (lane & 15);
                int colb = (kk + ((lane >> 4) << 3)) * 2;
                LDSM_X4(ah[mi][0], ah[mi][1], ah[mi][2], ah[mi][3],
                        base + r * MG_RSTR + colb);
                LDSM_X4(al[mi][0], al[mi][1], al[mi][2], al[mi][3],
                        base + MG_AT + r * MG_RSTR + colb);
            }
            uint32_t bh[8][2], bl[8][2];
            #pragma unroll
            for (int nb = 0; nb < 4; nb++) {
                int n = wn + nb * 16 + (lane & 7) + ((lane >> 4) << 3);
                int colb = (kk + (((lane >> 3) & 1) << 3)) * 2;
                LDSM_X4(bh[2 * nb][0], bh[2 * nb][1], bh[2 * nb + 1][0], bh[2 * nb + 1][1],
                        base + 2 * MG_AT + n * MG_RSTR + colb);
                LDSM_X4(bl[2 * nb][0], bl[2 * nb][1], bl[2 * nb + 1][0], bl[2 * nb + 1][1],
                        base + 2 * MG_AT + MG_BT + n * MG_RSTR + colb);
            }
            #pragma unroll
            for (int mi = 0; mi < 4; mi++)
                #pragma unroll
                for (int nj = 0; nj < 8; nj++) {
                    MMA_16816(acc[mi][nj], ah[mi], bh[nj]);
                    MMA_16816(acc[mi][nj], al[mi], bh[nj]);
                    MMA_16816(acc[mi][nj], ah[mi], bl[nj]);
                }
        }
        __syncthreads();
    }

    // epilogue
    #pragma unroll
    for (int mi = 0; mi < 4; mi++) {
        int r0 = bm + wm + mi * 16 + (lane >> 2);
        #pragma unroll
        for (int nj = 0; nj < 8; nj++) {
            int cn = bn + wn + nj * 8 + (lane & 3) * 2;
            float2 v0, v1;
            v0.x = acc[mi][nj][0]; v0.y = acc[mi][nj][1];
            v1.x = acc[mi][nj][2]; v1.y = acc[mi][nj][3];
            if (BIAS_RELU) {
                float b0 = bias[cn], b1 = bias[cn + 1];
                v0.x = fmaxf(v0.x + b0, 0.f); v0.y = fmaxf(v0.y + b1, 0.f);
                v1.x = fmaxf(v1.x + b0, 0.f); v1.y = fmaxf(v1.y + b1, 0.f);
            }
            if (SPLIT) {
                #pragma unroll
                for (int rr = 0; rr < 2; rr++) {
                    int r = r0 + rr * 8;
                    if (r < M) {
                        float2 v = rr ? v1 : v0;
                        __half hx = __float2half(v.x), hy = __float2half(v.y);
                        __half lx = __float2half(v.x - __half2float(hx));
                        __half ly = __float2half(v.y - __half2float(hy));
                        size_t o = ((size_t)r * N + cn) >> 1;
                        Chi[o] = __halves2half2(hx, hy);
                        Clo[o] = __halves2half2(lx, ly);
                    }
                }
            } else {
                if (r0 < M)     *(float2*)(Cf + (size_t)r0 * N + cn) = v0;
                if (r0 + 8 < M) *(float2*)(Cf + (size_t)(r0 + 8) * N + cn) = v1;
            }
        }
    }
}

// ================= SIMT GEMM (small layers L1-L3) =================
template <bool RELU, bool BIAS>
__global__ void __launch_bounds__(256) k_gemm(
    const float* __restrict__ A, const float* __restrict__ B,
    const float* __restrict__ bias, float* __restrict__ C,
    int M, int N, int K) {
    constexpr int BMx = 128, BNx = 64, BK = 16, TM = 8, TN = 4;
    constexpr int AST = BMx + 4;
    __shared__ float As[BK * AST];
    __shared__ float Bs[BK * BNx];
    const int tid = threadIdx.x;
    const int bm = blockIdx.y * BMx;
    const int bn = blockIdx.x * BNx;
    const int tx = tid & 15;
    const int ty = tid >> 4;
    const int ar = tid >> 2;
    const int ac = (tid & 3) * 4;
    const int br = tid >> 4;
    const int bc = (tid & 15) * 4;
    float acc[TM][TN] = {};
    for (int kt = 0; kt < K; kt += BK) {
        #pragma unroll
        for (int i = 0; i < 2; i++) {
            int r = ar + i * 64;
            int gr = bm + r;
            float4 v = make_float4(0.f, 0.f, 0.f, 0.f);
            if (gr < M) v = *(const float4*)(A + (size_t)gr * K + kt + ac);
            As[(ac + 0) * AST + r] = v.x;
            As[(ac + 1) * AST + r] = v.y;
            As[(ac + 2) * AST + r] = v.z;
            As[(ac + 3) * AST + r] = v.w;
        }
        {
            float4 v = *(const float4*)(B + (size_t)(kt + br) * N + bn + bc);
            *(float4*)(Bs + br * BNx + bc) = v;
        }
        __syncthreads();
        #pragma unroll
        for (int k = 0; k < BK; k++) {
            float ra[TM], rb[TN];
            float4 a0 = *(const float4*)(As + k * AST + ty * TM);
            float4 a1 = *(const float4*)(As + k * AST + ty * TM + 4);
            ra[0] = a0.x; ra[1] = a0.y; ra[2] = a0.z; ra[3] = a0.w;
            ra[4] = a1.x; ra[5] = a1.y; ra[6] = a1.z; ra[7] = a1.w;
            float4 b0 = *(const float4*)(Bs + k * BNx + tx * TN);
            rb[0] = b0.x; rb[1] = b0.y; rb[2] = b0.z; rb[3] = b0.w;
            #pragma unroll
            for (int m = 0; m < TM; m++)
                #pragma unroll
                for (int n = 0; n < TN; n++)
                    acc[m][n] += ra[m] * rb[n];
        }
        __syncthreads();
    }
    float bv[TN] = {0.f, 0.f, 0.f, 0.f};
    if (BIAS) {
        float4 t = *(const float4*)(bias + bn + tx * TN);
        bv[0] = t.x; bv[1] = t.y; bv[2] = t.z; bv[3] = t.w;
    }
    #pragma unroll
    for (int m = 0; m < TM; m++) {
        int gr = bm + ty * TM + m;
        if (gr < M) {
            float4 o;
            o.x = acc[m][0] + bv[0];
            o.y = acc[m][1] + bv[1];
            o.z = acc[m][2] + bv[2];
            o.w = acc[m][3] + bv[3];
            if (RELU) {
                o.x = fmaxf(o.x, 0.f); o.y = fmaxf(o.y, 0.f);
                o.z = fmaxf(o.z, 0.f); o.w = fmaxf(o.w, 0.f);
            }
            *(float4*)(C + (size_t)gr * N + bn + tx * TN) = o;
        }
    }
}

// ---------------- layer-0 GEMM (K=3, Fout=64, bias+relu) ----------------
__global__ void k_l0_gemm(const float* __restrict__ t, const float* __restrict__ W,
                          const float* __restrict__ b, float* __restrict__ y) {
    int idx = blockIdx.x * blockDim.x + threadIdx.x;
    if (idx >= NN * 64) return;
    int i = idx >> 6;
    int j = idx & 63;
    float acc = b[j];
    acc += t[i * 3 + 0] * W[0 * 64 + j];
    acc += t[i * 3 + 1] * W[1 * 64 + j];
    acc += t[i * 3 + 2] * W[2 * 64 + j];
    y[idx] = fmaxf(acc, 0.f);
}

// ---------------- layer-7 GEMM (K=256, Fout=2) with fused input relu ----
__global__ void k_l7_gemm(const float* __restrict__ x, const float* __restrict__ W,
                          float* __restrict__ h) {
    int gwarp = (blockIdx.x * blockDim.x + threadIdx.x) >> 5;
    int lane = threadIdx.x & 31;
    if (gwarp >= NN) return;
    const float4* xr = (const float4*)(x + (size_t)gwarp * 256);
    float a0 = 0.f, a1 = 0.f;
    #pragma unroll
    for (int it = 0; it < 2; it++) {
        int c4 = lane + it * 32;
        float4 v = xr[c4];
        v.x = fmaxf(v.x, 0.f); v.y = fmaxf(v.y, 0.f);
        v.z = fmaxf(v.z, 0.f); v.w = fmaxf(v.w, 0.f);
        int k = c4 * 4;
        a0 += v.x * W[(k + 0) * 2 + 0] + v.y * W[(k + 1) * 2 + 0]
            + v.z * W[(k + 2) * 2 + 0] + v.w * W[(k + 3) * 2 + 0];
        a1 += v.x * W[(k + 0) * 2 + 1] + v.y * W[(k + 1) * 2 + 1]
            + v.z * W[(k + 2) * 2 + 1] + v.w * W[(k + 3) * 2 + 1];
    }
    #pragma unroll
    for (int off = 16; off > 0; off >>= 1) {
        a0 += __shfl_down_sync(0xFFFFFFFFu, a0, off);
        a1 += __shfl_down_sync(0xFFFFFFFFu, a1, off);
    }
    if (lane == 0) {
        h[gwarp * 2 + 0] = a0;
        h[gwarp * 2 + 1] = a1;
    }
}

// ================= host orchestration =================
extern "C" void kernel_launch(void* const* d_in, const int* in_sizes, int n_in,
                              void* d_out, int out_size) {
    const float* x = (const float*)d_in[0];
    const int* ei  = (const int*)d_in[1];
    const int* row = ei;
    const int* col = ei + EE;
    const float* W[8];
    const float* b[8];
    for (int i = 0; i < 8; i++) {
        W[i] = (const float*)d_in[2 + 2 * i];
        b[i] = (const float*)d_in[3 + 2 * i];
    }
    float *bufA, *bufB, *dis, *enrm;
    __half *Ahi, *Alo, *Bhi, *Blo, *Wh, *Wl;
    int *cnt, *cur, *off, *bsum, *src;
    cudaGetSymbolAddress((void**)&bufA, g_bufA);
    cudaGetSymbolAddress((void**)&bufB, g_bufB);
    cudaGetSymbolAddress((void**)&Ahi,  g_Ahi);
    cudaGetSymbolAddress((void**)&Alo,  g_Alo);
    cudaGetSymbolAddress((void**)&Bhi,  g_Bhi);
    cudaGetSymbolAddress((void**)&Blo,  g_Blo);
    cudaGetSymbolAddress((void**)&Wh,   g_Wh);
    cudaGetSymbolAddress((void**)&Wl,   g_Wl);
    cudaGetSymbolAddress((void**)&cnt,  g_cnt);
    cudaGetSymbolAddress((void**)&cur,  g_cur);
    cudaGetSymbolAddress((void**)&off,  g_off);
    cudaGetSymbolAddress((void**)&bsum, g_bsum);
    cudaGetSymbolAddress((void**)&dis,  g_dis);
    cudaGetSymbolAddress((void**)&src,  g_src);
    cudaGetSymbolAddress((void**)&enrm, g_enrm);
    float* out = (float*)d_out;

    cudaFuncSetAttribute(k_mma_gemm<true, true>,
                         cudaFuncAttributeMaxDynamicSharedMemorySize, MG_SMEM);
    cudaFuncSetAttribute(k_mma_gemm<false, false>,
                         cudaFuncAttributeMaxDynamicSharedMemorySize, MG_SMEM);

    // ---- CSR build ----
    k_zero2<<<(NN + 255) / 256, 256>>>(cnt, cur);
    k_cnt<<<(EE + 255) / 256, 256>>>(col, cnt);
    k_scan1<<<SCAN_NB, SCAN_BS>>>(cnt, off, bsum);
    k_scan2<<<1, 128>>>(bsum);
    k_scan3<<<(NN + 255) / 256, 256>>>(off, bsum);
    k_disk<<<(NN + 255) / 256, 256>>>(cnt, dis);
    k_fill<<<(EE + 255) / 256, 256>>>(row, col, dis, off, cur, src, enrm);

    // ---- L0: 3 -> 64 ----
    k_gather1<3, false><<<(NN * 3 + 255) / 256, 256>>>(x, off, src, enrm, dis, nullptr, bufA);
    k_l0_gemm<<<(NN * 64 + 255) / 256, 256>>>(bufA, W[0], b[0], bufB);

    // ---- L1-L3 (SIMT fp32) ----
    k_gather4<64, false, false, false><<<(NN * 16 + 255) / 256, 256>>>(
        (const float4*)bufB, off, src, enrm, dis, nullptr, (float4*)bufA, nullptr, nullptr);
    k_gemm<true, true><<<dim3(1, (NN + 127) / 128), 256>>>(bufA, W[1], b[1], bufB, NN, 64, 64);

    k_gather4<64, false, false, false><<<(NN * 16 + 255) / 256, 256>>>(
        (const float4*)bufB, off, src, enrm, dis, nullptr, (float4*)bufA, nullptr, nullptr);
    k_gemm<true, true><<<dim3(1, (NN + 127) / 128), 256>>>(bufA, W[2], b[2], bufB, NN, 64, 64);

    k_gather4<64, false, false, false><<<(NN * 16 + 255) / 256, 256>>>(
        (const float4*)bufB, off, src, enrm, dis, nullptr, (float4*)bufA, nullptr, nullptr);
    k_gemm<true, true><<<dim3(2, (NN + 127) / 128), 256>>>(bufA, W[3], b[3], bufB, NN, 128, 64);

    // ---- L4: 128 -> 1024 (gather->split, mma with bias+relu, split output) ----
    k_gather4<128, false, false, true><<<(NN * 32 + 255) / 256, 256>>>(
        (const float4*)bufB, off, src, enrm, dis, nullptr, nullptr, (__half2*)Ahi, (__half2*)Alo);
    k_wsplit<<<(1024 * 128 + 255) / 256, 256>>>(W[4], Wh, Wl, 128, 1024);
    k_mma_gemm<true, true><<<dim3(4, (NN + 127) / 128), 256, MG_SMEM>>>(
        Ahi, Alo, Wh, Wl, b[4], nullptr, (__half2*)Bhi, (__half2*)Blo, NN, 1024, 128);

    // ---- L5: 1024 -> 512 (mma fp32 out; gather fuses bias+relu+split) ----
    k_wsplit<<<(512 * 1024 + 255) / 256, 256>>>(W[5], Wh, Wl, 1024, 512);
    k_mma_gemm<false, false><<<dim3(2, (NN + 127) / 128), 256, MG_SMEM>>>(
        Bhi, Blo, Wh, Wl, nullptr, bufA, nullptr, nullptr, NN, 512, 1024);
    k_gather4<512, true, true, true><<<(NN * 128 + 255) / 256, 256>>>(
        (const float4*)bufA, off, src, enrm, dis, b[5], nullptr, (__half2*)Ahi, (__half2*)Alo);

    // ---- L6: 512 -> 256 (mma fp32 out; gather fuses bias; relu in L7 load) ----
    k_wsplit<<<(256 * 512 + 255) / 256, 256>>>(W[6], Wh, Wl, 512, 256);
    k_mma_gemm<false, false><<<dim3(1, (NN + 127) / 128), 256, MG_SMEM>>>(
        Ahi, Alo, Wh, Wl, nullptr, bufB, nullptr, nullptr, NN, 256, 512);
    k_gather4<256, true, false, false><<<(NN * 64 + 255) / 256, 256>>>(
        (const float4*)bufB, off, src, enrm, dis, b[6], (float4*)bufA, nullptr, nullptr);

    // ---- L7: 256 -> 2 (relu fused into gemm load; gather fuses bias, writes d_out) ----
    k_l7_gemm<<<(NN * 32 + 255) / 256, 256>>>(bufA, W[7], bufB);
    k_gather1<2, true><<<(NN * 2 + 255) / 256, 256>>>(bufB, off, src, enrm, dis, b[7], out);
}

// round 10
// speedup vs baseline: 2.5266x; 1.0008x over previous
#include <cuda_runtime.h>
#include <cuda_fp16.h>
#include <cstdint>
#include <math.h>

#define NN 50000
#define EE 200000
#define SCAN_BS 512
#define SCAN_NB 98          // ceil(NN/512)

// ---------------- scratch (static device globals; allocation-free) ----------------
__device__ float g_bufA[(size_t)NN * 1024];
__device__ float g_bufB[(size_t)NN * 1024];
__device__ __half g_Ahi[(size_t)NN * 1024];
__device__ __half g_Alo[(size_t)NN * 1024];
__device__ __half g_Bhi[(size_t)NN * 1024];
__device__ __half g_Blo[(size_t)NN * 1024];
__device__ __half g_Wh[1024 * 1024];
__device__ __half g_Wl[1024 * 1024];
__device__ int   g_cnt[NN];
__device__ int   g_cur[NN];
__device__ int   g_off[NN + 1];
__device__ int   g_bsum[SCAN_NB];
__device__ float g_dis[NN];
__device__ int   g_src[EE];
__device__ float g_enrm[EE];

// ================= PTX helpers (arch-generic: sm_80+) =================
__device__ __forceinline__ uint32_t smem_to_u32(const void* p) {
    uint32_t a;
    asm("{ .reg .u64 t; cvta.to.shared.u64 t, %1; cvt.u32.u64 %0, t; }" : "=r"(a) : "l"(p));
    return a;
}
#define CP_ASYNC16(dst, src) \
    asm volatile("cp.async.cg.shared.global [%0], [%1], 16;" :: "r"(dst), "l"(src))
#define CP_COMMIT() asm volatile("cp.async.commit_group;" ::: "memory")
#define CP_WAIT(n)  asm volatile("cp.async.wait_group %0;" :: "n"(n) : "memory")
#define LDSM_X4(r0, r1, r2, r3, addr) \
    asm volatile("ldmatrix.sync.aligned.m8n8.x4.shared.b16 {%0,%1,%2,%3}, [%4];" \
        : "=r"(r0), "=r"(r1), "=r"(r2), "=r"(r3) : "r"(addr))
#define MMA_16816(c, a, b) \
    asm volatile("mma.sync.aligned.m16n8k16.row.col.f32.f16.f16.f32 " \
        "{%0,%1,%2,%3}, {%4,%5,%6,%7}, {%8,%9}, {%0,%1,%2,%3};" \
        : "+f"((c)[0]), "+f"((c)[1]), "+f"((c)[2]), "+f"((c)[3]) \
        : "r"((a)[0]), "r"((a)[1]), "r"((a)[2]), "r"((a)[3]), "r"((b)[0]), "r"((b)[1]))

// ================= CSR build =================
__global__ void k_zero2(int* __restrict__ a, int* __restrict__ b) {
    int i = blockIdx.x * blockDim.x + threadIdx.x;
    if (i < NN) { a[i] = 0; b[i] = 0; }
}
__global__ void k_cnt(const int* __restrict__ col, int* __restrict__ cnt) {
    int e = blockIdx.x * blockDim.x + threadIdx.x;
    if (e < EE) atomicAdd(&cnt[col[e]], 1);
}
__global__ void k_scan1(const int* __restrict__ cnt, int* __restrict__ off,
                        int* __restrict__ bsum) {
    __shared__ int sh[SCAN_BS];
    int tid = threadIdx.x;
    int i = blockIdx.x * SCAN_BS + tid;
    int v = (i < NN) ? cnt[i] : 0;
    sh[tid] = v;
    __syncthreads();
    #pragma unroll
    for (int d = 1; d < SCAN_BS; d <<= 1) {
        int t = (tid >= d) ? sh[tid - d] : 0;
        __syncthreads();
        sh[tid] += t;
        __syncthreads();
    }
    if (i < NN) off[i] = sh[tid] - v;          // exclusive
    if (tid == SCAN_BS - 1) bsum[blockIdx.x] = sh[tid];
}
__global__ void k_scan2(int* __restrict__ bsum) {
    __shared__ int sh[128];
    int tid = threadIdx.x;
    int v = (tid < SCAN_NB) ? bsum[tid] : 0;
    sh[tid] = v;
    __syncthreads();
    #pragma unroll
    for (int d = 1; d < 128; d <<= 1) {
        int t = (tid >= d) ? sh[tid - d] : 0;
        __syncthreads();
        sh[tid] += t;
        __syncthreads();
    }
    if (tid < SCAN_NB) bsum[tid] = sh[tid] - v;  // exclusive
}
__global__ void k_scan3(int* __restrict__ off, const int* __restrict__ bsum) {
    int i = blockIdx.x * blockDim.x + threadIdx.x;
    if (i < NN) off[i] += bsum[i / SCAN_BS];
    if (i == 0) off[NN] = EE;
}
__global__ void k_disk(const int* __restrict__ cnt, float* __restrict__ dis) {
    int i = blockIdx.x * blockDim.x + threadIdx.x;
    if (i < NN) dis[i] = rsqrtf((float)(cnt[i] + 1));
}
__global__ void k_fill(const int* __restrict__ row, const int* __restrict__ col,
                       const float* __restrict__ dis, const int* __restrict__ off,
                       int* __restrict__ cur, int* __restrict__ src,
                       float* __restrict__ enrm) {
    int e = blockIdx.x * blockDim.x + threadIdx.x;
    if (e >= EE) return;
    int r = row[e], c = col[e];
    int pos = off[c] + atomicAdd(&cur[c], 1);
    src[pos] = r;
    enrm[pos] = dis[r] * dis[c];
}

// ================= fused CSR gather aggregation =================
template <int F, bool BIAS, bool RELU, bool SPLIT>
__global__ void __launch_bounds__(256) k_gather4(
    const float4* __restrict__ h, const int* __restrict__ off,
    const int* __restrict__ src, const float* __restrict__ enrm,
    const float* __restrict__ dis, const float* __restrict__ bias,
    float4* __restrict__ outf, __half2* __restrict__ ohi, __half2* __restrict__ olo) {
    constexpr int FV = F / 4;
    int idx = blockIdx.x * blockDim.x + threadIdx.x;
    if (idx >= NN * FV) return;
    int i = idx / FV;
    int f4 = idx - i * FV;
    float d = dis[i];
    float s = d * d;
    float4 v = h[(size_t)i * FV + f4];
    float4 acc;
    acc.x = s * v.x; acc.y = s * v.y; acc.z = s * v.z; acc.w = s * v.w;
    int p0 = off[i], p1 = off[i + 1];
    for (int p = p0; p < p1; p++) {
        int sn = src[p];
        float w = enrm[p];
        float4 u = h[(size_t)sn * FV + f4];
        acc.x += w * u.x; acc.y += w * u.y; acc.z += w * u.z; acc.w += w * u.w;
    }
    if (BIAS) {
        const float4 bv = *(const float4*)(bias + f4 * 4);
        acc.x += bv.x; acc.y += bv.y; acc.z += bv.z; acc.w += bv.w;
    }
    if (RELU) {
        acc.x = fmaxf(acc.x, 0.f); acc.y = fmaxf(acc.y, 0.f);
        acc.z = fmaxf(acc.z, 0.f); acc.w = fmaxf(acc.w, 0.f);
    }
    if (SPLIT) {
        __half hx = __float2half(acc.x), hy = __float2half(acc.y);
        __half hz = __float2half(acc.z), hw = __float2half(acc.w);
        __half lx = __float2half(acc.x - __half2float(hx));
        __half ly = __float2half(acc.y - __half2float(hy));
        __half lz = __float2half(acc.z - __half2float(hz));
        __half lw = __float2half(acc.w - __half2float(hw));
        ohi[(size_t)idx * 2 + 0] = __halves2half2(hx, hy);
        ohi[(size_t)idx * 2 + 1] = __halves2half2(hz, hw);
        olo[(size_t)idx * 2 + 0] = __halves2half2(lx, ly);
        olo[(size_t)idx * 2 + 1] = __halves2half2(lz, lw);
    } else {
        outf[idx] = acc;
    }
}

// scalar variant for F=3 and F=2
template <int F, bool BIAS>
__global__ void k_gather1(const float* __restrict__ h, const int* __restrict__ off,
                          const int* __restrict__ src, const float* __restrict__ enrm,
                          const float* __restrict__ dis, const float* __restrict__ bias,
                          float* __restrict__ outf) {
    int idx = blockIdx.x * blockDim.x + threadIdx.x;
    if (idx >= NN * F) return;
    int i = idx / F;
    int f = idx - i * F;
    float d = dis[i];
    float acc = d * d * h[(size_t)i * F + f];
    int p0 = off[i], p1 = off[i + 1];
    for (int p = p0; p < p1; p++)
        acc += enrm[p] * h[(size_t)src[p] * F + f];
    if (BIAS) acc += bias[f];
    outf[idx] = acc;
}

// ================= split-fp16 weight transpose =================
__global__ void k_wsplit(const float* __restrict__ W, __half* __restrict__ Wh,
                         __half* __restrict__ Wl, int K, int N) {
    int idx = blockIdx.x * blockDim.x + threadIdx.x;
    if (idx >= N * K) return;
    int n = idx / K;
    int k = idx - n * K;
    float v = W[(size_t)k * N + n];
    __half h = __float2half(v);
    Wh[idx] = h;
    Wl[idx] = __float2half(v - __half2float(h));
}

// ================= fused-product mma.sync split-fp16 GEMM =================
// C = AhWh + AlWh + AhWl, all three products issued per K-chunk (single K sweep).
// CTA tile 128x256, BK=32, 8 warps (2m x 4n), warp tile 64x64.
// Products are swept at the OUTER level so consecutive MMAs never share an
// accumulator (no RAW chains on the tensor pipe).
// Stage layout (61440 B): [Ah 10240][Al 10240][Bh 20480][Bl 20480]; 2 stages.
#define MG_RSTR  80
#define MG_AT    10240
#define MG_BT    20480
#define MG_ST4   61440
#define MG_SMEM  (2 * MG_ST4)

__device__ __forceinline__ void mg_load4(
    const __half* __restrict__ Ah_, const __half* __restrict__ Al_,
    const __half* __restrict__ Bh_, const __half* __restrict__ Bl_,
    int M, int K, int bm, int bn, int koff, uint32_t st, int tid) {
    #pragma unroll
    for (int i = 0; i < 2; i++) {
        int idx = tid + i * 256;
        int r = idx >> 2, ch = idx & 3;
        int gr = bm + r;
        if (gr >= M) gr = M - 1;
        CP_ASYNC16(st + r * MG_RSTR + ch * 16,
                   (const void*)(Ah_ + (size_t)gr * K + koff + ch * 8));
    }
    #pragma unroll
    for (int i = 0; i < 2; i++) {
        int idx = tid + i * 256;
        int r = idx >> 2, ch = idx & 3;
        int gr = bm + r;
        if (gr >= M) gr = M - 1;
        CP_ASYNC16(st + MG_AT + r * MG_RSTR + ch * 16,
                   (const void*)(Al_ + (size_t)gr * K + koff + ch * 8));
    }
    #pragma unroll
    for (int i = 0; i < 4; i++) {
        int idx = tid + i * 256;
        int r = idx >> 2, ch = idx & 3;
        CP_ASYNC16(st + 2 * MG_AT + r * MG_RSTR + ch * 16,
                   (const void*)(Bh_ + (size_t)(bn + r) * K + koff + ch * 8));
    }
    #pragma unroll
    for (int i = 0; i < 4; i++) {
        int idx = tid + i * 256;
        int r = idx >> 2, ch = idx & 3;
        CP_ASYNC16(st + 2 * MG_AT + MG_BT + r * MG_RSTR + ch * 16,
                   (const void*)(Bl_ + (size_t)(bn + r) * K + koff + ch * 8));
    }
    CP_COMMIT();
}

template <bool BIAS_RELU, bool SPLIT>
__global__ void __launch_bounds__(256) k_mma_gemm(
    const __half* __restrict__ Ahi, const __half* __restrict__ Alo,
    const __half* __restrict__ Bhi, const __half* __restrict__ Blo,
    const float* __restrict__ bias, float* __restrict__ Cf,
    __half2* __restrict__ Chi, __half2* __restrict__ Clo,
    int M, int N, int K) {
    extern __shared__ __align__(16) char smx[];
    const uint32_t sbase = smem_to_u32(smx);
    const int tid = threadIdx.x;
    const int lane = tid & 31;
    const int wid = tid >> 5;
    const int wm = (wid & 1) * 64;
    const int wn = (wid >> 1) * 64;
    const int bm = blockIdx.y * 128;
    const int bn = blockIdx.x * 256;

    const int CK = K / 32;

    float acc[4][8][4];
    #pragma unroll
    for (int i = 0; i < 4; i++)
        #pragma unroll
        for (int j = 0; j < 8; j++)
            #pragma unroll
            for (int q = 0; q < 4; q++) acc[i][j][q] = 0.f;

    mg_load4(Ahi, Alo, Bhi, Blo, M, K, bm, bn, 0, sbase, tid);

    for (int c = 0; c < CK; c++) {
        const int s = c & 1;
        if (c + 1 < CK) {
            mg_load4(Ahi, Alo, Bhi, Blo, M, K, bm, bn, (c + 1) * 32,
                     sbase + (s ^ 1) * MG_ST4, tid);
            CP_WAIT(1);
        } else {
            CP_WAIT(0);
        }
        __syncthreads();

        const uint32_t base = sbase + s * MG_ST4;
        #pragma unroll
        for (int kk = 0; kk < 32; kk += 16) {
            uint32_t ah[4][4], al[4][4];
            #pragma unroll
            for (int mi = 0; mi < 4; mi++) {
                int r = wm + mi * 16 + (lane & 15);
                int colb = (kk + ((lane >> 4) << 3)) * 2;
                LDSM_X4(ah[mi][0], ah[mi][1], ah[mi][2], ah[mi][3],
                        base + r * MG_RSTR + colb);
                LDSM_X4(al[mi][0], al[mi][1], al[mi][2], al[mi][3],
                        base + MG_AT + r * MG_RSTR + colb);
            }
            uint32_t bh[8][2], bl[8][2];
            #pragma unroll
            for (int nb = 0; nb < 4; nb++) {
                int n = wn + nb * 16 + (lane & 7) + ((lane >> 4) << 3);
                int colb = (kk + (((lane >> 3) & 1) << 3)) * 2;
                LDSM_X4(bh[2 * nb][0], bh[2 * nb][1], bh[2 * nb + 1][0], bh[2 * nb + 1][1],
                        base + 2 * MG_AT + n * MG_RSTR + colb);
                LDSM_X4(bl[2 * nb][0], bl[2 * nb][1], bl[2 * nb + 1][0], bl[2 * nb + 1][1],
                        base + 2 * MG_AT + MG_BT + n * MG_RSTR + colb);
            }
            // product-major sweeps: 32 independent accumulators between
            // touches of the same acc -> no HMMA RAW stalls.
            #pragma unroll
            for (int mi = 0; mi < 4; mi++)
                #pragma unroll
                for (int nj = 0; nj < 8; nj++)
                    MMA_16816(acc[mi][nj], ah[mi], bh[nj]);
            #pragma unroll
            for (int mi = 0; mi < 4; mi++)
                #pragma unroll
                for (int nj = 0; nj < 8; nj++)
                    MMA_16816(acc[mi][nj], al[mi], bh[nj]);
            #pragma unroll
            for (int mi = 0; mi < 4; mi++)
                #pragma unroll
                for (int nj = 0; nj < 8; nj++)
                    MMA_16816(acc[mi][nj], ah[mi], bl[nj]);
        }
        __syncthreads();
    }

    // epilogue
    #pragma unroll
    for (int mi = 0; mi < 4; mi++) {
        int r0 = bm + wm + mi * 16 + (lane >> 2);
        #pragma unroll
        for (int nj = 0; nj < 8; nj++) {
            int cn = bn + wn + nj * 8 + (lane & 3) * 2;
            float2 v0, v1;
            v0.x = acc[mi][nj][0]; v0.y = acc[mi][nj][1];
            v1.x = acc[mi][nj][2]; v1.y = acc[mi][nj][3];
            if (BIAS_RELU) {
                float b0 = bias[cn], b1 = bias[cn + 1];
                v0.x = fmaxf(v0.x + b0, 0.f); v0.y = fmaxf(v0.y + b1, 0.f);
                v1.x = fmaxf(v1.x + b0, 0.f); v1.y = fmaxf(v1.y + b1, 0.f);
            }
            if (SPLIT) {
                #pragma unroll
                for (int rr = 0; rr < 2; rr++) {
                    int r = r0 + rr * 8;
                    if (r < M) {
                        float2 v = rr ? v1 : v0;
                        __half hx = __float2half(v.x), hy = __float2half(v.y);
                        __half lx = __float2half(v.x - __half2float(hx));
                        __half ly = __float2half(v.y - __half2float(hy));
                        size_t o = ((size_t)r * N + cn) >> 1;
                        Chi[o] = __halves2half2(hx, hy);
                        Clo[o] = __halves2half2(lx, ly);
                    }
                }
            } else {
                if (r0 < M)     *(float2*)(Cf + (size_t)r0 * N + cn) = v0;
                if (r0 + 8 < M) *(float2*)(Cf + (size_t)(r0 + 8) * N + cn) = v1;
            }
        }
    }
}

// ================= SIMT GEMM (small layers L1-L3) =================
template <bool RELU, bool BIAS>
__global__ void __launch_bounds__(256) k_gemm(
    const float* __restrict__ A, const float* __restrict__ B,
    const float* __restrict__ bias, float* __restrict__ C,
    int M, int N, int K) {
    constexpr int BMx = 128, BNx = 64, BK = 16, TM = 8, TN = 4;
    constexpr int AST = BMx + 4;
    __shared__ float As[BK * AST];
    __shared__ float Bs[BK * BNx];
    const int tid = threadIdx.x;
    const int bm = blockIdx.y * BMx;
    const int bn = blockIdx.x * BNx;
    const int tx = tid & 15;
    const int ty = tid >> 4;
    const int ar = tid >> 2;
    const int ac = (tid & 3) * 4;
    const int br = tid >> 4;
    const int bc = (tid & 15) * 4;
    float acc[TM][TN] = {};
    for (int kt = 0; kt < K; kt += BK) {
        #pragma unroll
        for (int i = 0; i < 2; i++) {
            int r = ar + i * 64;
            int gr = bm + r;
            float4 v = make_float4(0.f, 0.f, 0.f, 0.f);
            if (gr < M) v = *(const float4*)(A + (size_t)gr * K + kt + ac);
            As[(ac + 0) * AST + r] = v.x;
            As[(ac + 1) * AST + r] = v.y;
            As[(ac + 2) * AST + r] = v.z;
            As[(ac + 3) * AST + r] = v.w;
        }
        {
            float4 v = *(const float4*)(B + (size_t)(kt + br) * N + bn + bc);
            *(float4*)(Bs + br * BNx + bc) = v;
        }
        __syncthreads();
        #pragma unroll
        for (int k = 0; k < BK; k++) {
            float ra[TM], rb[TN];
            float4 a0 = *(const float4*)(As + k * AST + ty * TM);
            float4 a1 = *(const float4*)(As + k * AST + ty * TM + 4);
            ra[0] = a0.x; ra[1] = a0.y; ra[2] = a0.z; ra[3] = a0.w;
            ra[4] = a1.x; ra[5] = a1.y; ra[6] = a1.z; ra[7] = a1.w;
            float4 b0 = *(const float4*)(Bs + k * BNx + tx * TN);
            rb[0] = b0.x; rb[1] = b0.y; rb[2] = b0.z; rb[3] = b0.w;
            #pragma unroll
            for (int m = 0; m < TM; m++)
                #pragma unroll
                for (int n = 0; n < TN; n++)
                    acc[m][n] += ra[m] * rb[n];
        }
        __syncthreads();
    }
    float bv[TN] = {0.f, 0.f, 0.f, 0.f};
    if (BIAS) {
        float4 t = *(const float4*)(bias + bn + tx * TN);
        bv[0] = t.x; bv[1] = t.y; bv[2] = t.z; bv[3] = t.w;
    }
    #pragma unroll
    for (int m = 0; m < TM; m++) {
        int gr = bm + ty * TM + m;
        if (gr < M) {
            float4 o;
            o.x = acc[m][0] + bv[0];
            o.y = acc[m][1] + bv[1];
            o.z = acc[m][2] + bv[2];
            o.w = acc[m][3] + bv[3];
            if (RELU) {
                o.x = fmaxf(o.x, 0.f); o.y = fmaxf(o.y, 0.f);
                o.z = fmaxf(o.z, 0.f); o.w = fmaxf(o.w, 0.f);
            }
            *(float4*)(C + (size_t)gr * N + bn + tx * TN) = o;
        }
    }
}

// ---------------- layer-0 GEMM (K=3, Fout=64, bias+relu) ----------------
__global__ void k_l0_gemm(const float* __restrict__ t, const float* __restrict__ W,
                          const float* __restrict__ b, float* __restrict__ y) {
    int idx = blockIdx.x * blockDim.x + threadIdx.x;
    if (idx >= NN * 64) return;
    int i = idx >> 6;
    int j = idx & 63;
    float acc = b[j];
    acc += t[i * 3 + 0] * W[0 * 64 + j];
    acc += t[i * 3 + 1] * W[1 * 64 + j];
    acc += t[i * 3 + 2] * W[2 * 64 + j];
    y[idx] = fmaxf(acc, 0.f);
}

// ---------------- layer-7 GEMM (K=256, Fout=2) with fused input relu ----
__global__ void k_l7_gemm(const float* __restrict__ x, const float* __restrict__ W,
                          float* __restrict__ h) {
    int gwarp = (blockIdx.x * blockDim.x + threadIdx.x) >> 5;
    int lane = threadIdx.x & 31;
    if (gwarp >= NN) return;
    const float4* xr = (const float4*)(x + (size_t)gwarp * 256);
    float a0 = 0.f, a1 = 0.f;
    #pragma unroll
    for (int it = 0; it < 2; it++) {
        int c4 = lane + it * 32;
        float4 v = xr[c4];
        v.x = fmaxf(v.x, 0.f); v.y = fmaxf(v.y, 0.f);
        v.z = fmaxf(v.z, 0.f); v.w = fmaxf(v.w, 0.f);
        int k = c4 * 4;
        a0 += v.x * W[(k + 0) * 2 + 0] + v.y * W[(k + 1) * 2 + 0]
            + v.z * W[(k + 2) * 2 + 0] + v.w * W[(k + 3) * 2 + 0];
        a1 += v.x * W[(k + 0) * 2 + 1] + v.y * W[(k + 1) * 2 + 1]
            + v.z * W[(k + 2) * 2 + 1] + v.w * W[(k + 3) * 2 + 1];
    }
    #pragma unroll
    for (int off = 16; off > 0; off >>= 1) {
        a0 += __shfl_down_sync(0xFFFFFFFFu, a0, off);
        a1 += __shfl_down_sync(0xFFFFFFFFu, a1, off);
    }
    if (lane == 0) {
        h[gwarp * 2 + 0] = a0;
        h[gwarp * 2 + 1] = a1;
    }
}

// ================= host orchestration =================
extern "C" void kernel_launch(void* const* d_in, const int* in_sizes, int n_in,
                              void* d_out, int out_size) {
    const float* x = (const float*)d_in[0];
    const int* ei  = (const int*)d_in[1];
    const int* row = ei;
    const int* col = ei + EE;
    const float* W[8];
    const float* b[8];
    for (int i = 0; i < 8; i++) {
        W[i] = (const float*)d_in[2 + 2 * i];
        b[i] = (const float*)d_in[3 + 2 * i];
    }
    float *bufA, *bufB, *dis, *enrm;
    __half *Ahi, *Alo, *Bhi, *Blo, *Wh, *Wl;
    int *cnt, *cur, *off, *bsum, *src;
    cudaGetSymbolAddress((void**)&bufA, g_bufA);
    cudaGetSymbolAddress((void**)&bufB, g_bufB);
    cudaGetSymbolAddress((void**)&Ahi,  g_Ahi);
    cudaGetSymbolAddress((void**)&Alo,  g_Alo);
    cudaGetSymbolAddress((void**)&Bhi,  g_Bhi);
    cudaGetSymbolAddress((void**)&Blo,  g_Blo);
    cudaGetSymbolAddress((void**)&Wh,   g_Wh);
    cudaGetSymbolAddress((void**)&Wl,   g_Wl);
    cudaGetSymbolAddress((void**)&cnt,  g_cnt);
    cudaGetSymbolAddress((void**)&cur,  g_cur);
    cudaGetSymbolAddress((void**)&off,  g_off);
    cudaGetSymbolAddress((void**)&bsum, g_bsum);
    cudaGetSymbolAddress((void**)&dis,  g_dis);
    cudaGetSymbolAddress((void**)&src,  g_src);
    cudaGetSymbolAddress((void**)&enrm, g_enrm);
    float* out = (float*)d_out;

    cudaFuncSetAttribute(k_mma_gemm<true, true>,
                         cudaFuncAttributeMaxDynamicSharedMemorySize, MG_SMEM);
    cudaFuncSetAttribute(k_mma_gemm<false, false>,
                         cudaFuncAttributeMaxDynamicSharedMemorySize, MG_SMEM);

    // ---- CSR build ----
    k_zero2<<<(NN + 255) / 256, 256>>>(cnt, cur);
    k_cnt<<<(EE + 255) / 256, 256>>>(col, cnt);
    k_scan1<<<SCAN_NB, SCAN_BS>>>(cnt, off, bsum);
    k_scan2<<<1, 128>>>(bsum);
    k_scan3<<<(NN + 255) / 256, 256>>>(off, bsum);
    k_disk<<<(NN + 255) / 256, 256>>>(cnt, dis);
    k_fill<<<(EE + 255) / 256, 256>>>(row, col, dis, off, cur, src, enrm);

    // ---- L0: 3 -> 64 ----
    k_gather1<3, false><<<(NN * 3 + 255) / 256, 256>>>(x, off, src, enrm, dis, nullptr, bufA);
    k_l0_gemm<<<(NN * 64 + 255) / 256, 256>>>(bufA, W[0], b[0], bufB);

    // ---- L1-L3 (SIMT fp32) ----
    k_gather4<64, false, false, false><<<(NN * 16 + 255) / 256, 256>>>(
        (const float4*)bufB, off, src, enrm, dis, nullptr, (float4*)bufA, nullptr, nullptr);
    k_gemm<true, true><<<dim3(1, (NN + 127) / 128), 256>>>(bufA, W[1], b[1], bufB, NN, 64, 64);

    k_gather4<64, false, false, false><<<(NN * 16 + 255) / 256, 256>>>(
        (const float4*)bufB, off, src, enrm, dis, nullptr, (float4*)bufA, nullptr, nullptr);
    k_gemm<true, true><<<dim3(1, (NN + 127) / 128), 256>>>(bufA, W[2], b[2], bufB, NN, 64, 64);

    k_gather4<64, false, false, false><<<(NN * 16 + 255) / 256, 256>>>(
        (const float4*)bufB, off, src, enrm, dis, nullptr, (float4*)bufA, nullptr, nullptr);
    k_gemm<true, true><<<dim3(2, (NN + 127) / 128), 256>>>(bufA, W[3], b[3], bufB, NN, 128, 64);

    // ---- L4: 128 -> 1024 (gather->split, mma with bias+relu, split output) ----
    k_gather4<128, false, false, true><<<(NN * 32 + 255) / 256, 256>>>(
        (const float4*)bufB, off, src, enrm, dis, nullptr, nullptr, (__half2*)Ahi, (__half2*)Alo);
    k_wsplit<<<(1024 * 128 + 255) / 256, 256>>>(W[4], Wh, Wl, 128, 1024);
    k_mma_gemm<true, true><<<dim3(4, (NN + 127) / 128), 256, MG_SMEM>>>(
        Ahi, Alo, Wh, Wl, b[4], nullptr, (__half2*)Bhi, (__half2*)Blo, NN, 1024, 128);

    // ---- L5: 1024 -> 512 (mma fp32 out; gather fuses bias+relu+split) ----
    k_wsplit<<<(512 * 1024 + 255) / 256, 256>>>(W[5], Wh, Wl, 1024, 512);
    k_mma_gemm<false, false><<<dim3(2, (NN + 127) / 128), 256, MG_SMEM>>>(
        Bhi, Blo, Wh, Wl, nullptr, bufA, nullptr, nullptr, NN, 512, 1024);
    k_gather4<512, true, true, true><<<(NN * 128 + 255) / 256, 256>>>(
        (const float4*)bufA, off, src, enrm, dis, b[5], nullptr, (__half2*)Ahi, (__half2*)Alo);

    // ---- L6: 512 -> 256 (mma fp32 out; gather fuses bias; relu in L7 load) ----
    k_wsplit<<<(256 * 512 + 255) / 256, 256>>>(W[6], Wh, Wl, 512, 256);
    k_mma_gemm<false, false><<<dim3(1, (NN + 127) / 128), 256, MG_SMEM>>>(
        Ahi, Alo, Wh, Wl, nullptr, bufB, nullptr, nullptr, NN, 256, 512);
    k_gather4<256, true, false, false><<<(NN * 64 + 255) / 256, 256>>>(
        (const float4*)bufB, off, src, enrm, dis, b[6], (float4*)bufA, nullptr, nullptr);

    // ---- L7: 256 -> 2 (relu fused into gemm load; gather fuses bias, writes d_out) ----
    k_l7_gemm<<<(NN * 32 + 255) / 256, 256>>>(bufA, W[7], bufB);
    k_gather1<2, true><<<(NN * 2 + 255) / 256, 256>>>(bufB, off, src, enrm, dis, b[7], out);
}